// round 2
// baseline (speedup 1.0000x reference)
#include <cuda_runtime.h>

#define B_   32
#define D_   256
#define HW_  4096
#define N_   131072          // B*H*W
#define K_   1024
#define TOTQ 33554432        // B*D*H*W

// Output layout (flattened tuple, float32):
//   [0, 33554432)                quantized_ste
//   [33554432]                   commitment_loss
//   [33554433, 33685505)         encoding_indices (as float)
//   [33685505, 33686529)         new_cluster_size
//   [33686529, 33948673)         new_ema_embedding
#define OUT_LOSS 33554432
#define OUT_IDX  33554433
#define OUT_CS   33685505
#define OUT_EMB  33686529

// Device scratch (no allocations allowed)
__device__ float  g_Et[D_ * K_];     // E transposed, d-major: Et[d*K + k]
__device__ float  g_enorm[K_];
__device__ int    g_idx[N_];
__device__ float  g_counts[K_];
__device__ float  g_dw[K_ * D_];
__device__ double g_loss;

// ---------------------------------------------------------------------------
// Kernel 0: zero scratch, compute ||e_k||^2, build transposed E
// ---------------------------------------------------------------------------
__global__ void prep_kernel(const float* __restrict__ emb) {
    int tid = blockIdx.x * blockDim.x + threadIdx.x;   // 262144 threads
    if (tid < K_ * D_) {
        g_dw[tid] = 0.0f;
        int k = tid & (K_ - 1);
        int d = tid >> 10;
        g_Et[tid] = emb[k * D_ + d];                   // Et[d*1024 + k]
    }
    if (tid < K_) {
        g_counts[tid] = 0.0f;
        const float* e = emb + tid * D_;
        float s = 0.0f;
        #pragma unroll 8
        for (int d = 0; d < D_; ++d) { float v = e[d]; s += v * v; }
        g_enorm[tid] = s;
    }
    if (tid == 0) g_loss = 0.0;
}

// ---------------------------------------------------------------------------
// Kernel 1: fused distance GEMM + argmin.
// Block = 128 n-rows. Loop over 8 k-chunks of 128 codes; within each chunk,
// stream D in 32-wide smem tiles; 8x8 register micro-tile per thread.
// Running per-row (min, argmin) in smem, tie-break = lowest index.
// ---------------------------------------------------------------------------
__global__ void __launch_bounds__(256, 2)
dist_argmin_kernel(const float* __restrict__ z, float* __restrict__ out_idx_f) {
    __shared__ float Zs[32][128];
    __shared__ float Es[32][128];
    __shared__ float rmin[128];
    __shared__ int   ridx[128];

    const int tid = threadIdx.x;
    const int n0  = blockIdx.x * 128;
    const int b   = n0 >> 12;            // n0 / 4096
    const int hw0 = n0 & 4095;
    const float* zb = z + (size_t)b * D_ * HW_ + hw0;

    const int tk = tid & 15;             // 16 threads along k
    const int tn = tid >> 4;             // 16 thread-groups along n

    if (tid < 128) { rmin[tid] = 3.4e38f; ridx[tid] = 0; }

    const int w    = tid >> 5;           // warp id (0..7) for tile loads
    const int lane = tid & 31;

    for (int kc = 0; kc < 8; ++kc) {
        float acc[8][8];
        #pragma unroll
        for (int i = 0; i < 8; ++i)
            #pragma unroll
            for (int j = 0; j < 8; ++j) acc[i][j] = 0.0f;

        const int k0 = kc * 128;

        for (int dc = 0; dc < 8; ++dc) {
            __syncthreads();
            // Load Zs[32][128] and Es[32][128]; each warp loads 4 d-rows.
            #pragma unroll
            for (int r = 0; r < 4; ++r) {
                int dd = w * 4 + r;
                int d  = dc * 32 + dd;
                float4 zv = *(const float4*)(zb + (size_t)d * HW_ + lane * 4);
                *(float4*)&Zs[dd][lane * 4] = zv;
                float4 ev = *(const float4*)(g_Et + (size_t)d * K_ + k0 + lane * 4);
                *(float4*)&Es[dd][lane * 4] = ev;
            }
            __syncthreads();

            #pragma unroll
            for (int dd = 0; dd < 32; ++dd) {
                float4 a0 = *(float4*)&Zs[dd][tn * 8];
                float4 a1 = *(float4*)&Zs[dd][tn * 8 + 4];
                float4 b0 = *(float4*)&Es[dd][tk * 8];
                float4 b1 = *(float4*)&Es[dd][tk * 8 + 4];
                float av[8] = {a0.x, a0.y, a0.z, a0.w, a1.x, a1.y, a1.z, a1.w};
                float bv[8] = {b0.x, b0.y, b0.z, b0.w, b1.x, b1.y, b1.z, b1.w};
                #pragma unroll
                for (int i = 0; i < 8; ++i)
                    #pragma unroll
                    for (int j = 0; j < 8; ++j)
                        acc[i][j] = fmaf(av[i], bv[j], acc[i][j]);
            }
        }

        // Epilogue for this k-chunk: score = ||e||^2 - 2*dot, update running min.
        #pragma unroll
        for (int i = 0; i < 8; ++i) {
            float best = 3.4e38f; int bi = 0;
            #pragma unroll
            for (int j = 0; j < 8; ++j) {
                int k = k0 + tk * 8 + j;
                float s = g_enorm[k] - 2.0f * acc[i][j];
                if (s < best) { best = s; bi = k; }    // j ascending -> first min
            }
            #pragma unroll
            for (int off = 8; off > 0; off >>= 1) {
                float ov = __shfl_down_sync(0xffffffffu, best, off, 16);
                int   oi = __shfl_down_sync(0xffffffffu, bi,   off, 16);
                if (ov < best || (ov == best && oi < bi)) { best = ov; bi = oi; }
            }
            if (tk == 0) {
                int ln = tn * 8 + i;                   // owned exclusively by this thread
                if (best < rmin[ln]) { rmin[ln] = best; ridx[ln] = bi; }
            }
        }
    }
    __syncthreads();

    if (tid < 128) {
        int n = n0 + tid;
        int idx = ridx[tid];
        g_idx[n] = idx;
        out_idx_f[n] = (float)idx;
        atomicAdd(&g_counts[idx], 1.0f);
    }
}

// ---------------------------------------------------------------------------
// Kernel 2: gather quantized, accumulate commitment-loss sum, scatter dw.
// One thread per z element (b,d,hw) with hw fastest -> coalesced z/out.
// ---------------------------------------------------------------------------
__global__ void gather_loss_dw_kernel(const float* __restrict__ z,
                                      const float* __restrict__ emb,
                                      float* __restrict__ out_q) {
    int e  = blockIdx.x * 256 + threadIdx.x;   // [0, 33554432)
    int hw = e & 4095;
    int bd = e >> 12;
    int d  = bd & 255;
    int b  = bd >> 8;
    int n  = (b << 12) | hw;

    int   idx = g_idx[n];
    float q   = emb[idx * D_ + d];
    float zv  = z[e];
    out_q[e]  = q;
    float diff = zv - q;
    float sq   = diff * diff;
    atomicAdd(&g_dw[idx * D_ + d], zv);

    // block reduction of sq
    #pragma unroll
    for (int off = 16; off > 0; off >>= 1)
        sq += __shfl_down_sync(0xffffffffu, sq, off);
    __shared__ float wsum[8];
    int lane = threadIdx.x & 31, wid = threadIdx.x >> 5;
    if (lane == 0) wsum[wid] = sq;
    __syncthreads();
    if (wid == 0) {
        float v = (lane < 8) ? wsum[lane] : 0.0f;
        #pragma unroll
        for (int off = 4; off > 0; off >>= 1)
            v += __shfl_down_sync(0xffffffffu, v, off);
        if (lane == 0) atomicAdd(&g_loss, (double)v);
    }
}

// ---------------------------------------------------------------------------
// Kernel 3: EMA updates + loss finalize
// ---------------------------------------------------------------------------
__global__ void finalize_kernel(const float* __restrict__ ema_cs,
                                const float* __restrict__ ema_emb,
                                float* __restrict__ out) {
    int i = blockIdx.x * 256 + threadIdx.x;    // 262144 threads
    const float decay = 0.99f;
    const float omd   = (float)(1.0 - 0.99);   // matches Python (1.0 - DECAY) -> f32
    if (i < K_ * D_) out[OUT_EMB + i] = decay * ema_emb[i] + omd * g_dw[i];
    if (i < K_)      out[OUT_CS  + i] = decay * ema_cs[i]  + omd * g_counts[i];
    if (i == 0)      out[OUT_LOSS]    = 0.25f * (float)(g_loss / (double)TOTQ);
}

// ---------------------------------------------------------------------------
extern "C" void kernel_launch(void* const* d_in, const int* in_sizes, int n_in,
                              void* d_out, int out_size) {
    const float* z       = (const float*)d_in[0];
    const float* emb     = (const float*)d_in[1];
    const float* ema_cs  = (const float*)d_in[2];
    const float* ema_emb = (const float*)d_in[3];
    float* out = (float*)d_out;

    prep_kernel<<<1024, 256>>>(emb);
    dist_argmin_kernel<<<N_ / 128, 256>>>(z, out + OUT_IDX);
    gather_loss_dw_kernel<<<TOTQ / 256, 256>>>(z, emb, out);
    finalize_kernel<<<1024, 256>>>(ema_cs, ema_emb, out);
}

// round 4
// speedup vs baseline: 1.0294x; 1.0294x over previous
#include <cuda_runtime.h>

#define B_   32
#define D_   256
#define HW_  4096
#define N_   131072          // B*H*W
#define K_   1024
#define TOTQ 33554432        // B*D*H*W

// Output layout (flattened tuple, float32):
//   [0, 33554432)                quantized_ste
//   [33554432]                   commitment_loss
//   [33554433, 33685505)         encoding_indices (as float)
//   [33685505, 33686529)         new_cluster_size
//   [33686529, 33948673)         new_ema_embedding
#define OUT_LOSS 33554432
#define OUT_IDX  33554433
#define OUT_CS   33685505
#define OUT_EMB  33686529

// Device scratch (no allocations allowed)
__device__ float  g_Et[D_ * K_];     // E transposed, d-major: Et[d*K + k]
__device__ float  g_enorm[K_];
__device__ int    g_idx[N_];
__device__ float  g_counts[K_];
__device__ float  g_dw[K_ * D_];
__device__ double g_loss;

// Packed fp32x2 FMA (sm_103a): 2 FMAs/instruction, fma.rn per lane (bit-exact).
#define FMA_F32X2(d, a, b, c) \
    asm("fma.rn.f32x2 %0, %1, %2, %3;" : "=l"(d) : "l"(a), "l"(b), "l"(c))
#define PACK_F32X2F(out, lo, hi) \
    asm("mov.b64 %0, {%1, %2};" : "=l"(out) : "f"(lo), "f"(hi))
#define UNPACK_F32X2F(lo, hi, in) \
    asm("mov.b64 {%0, %1}, %2;" : "=f"(lo), "=f"(hi) : "l"(in))

// ---------------------------------------------------------------------------
// Kernel 0: zero scratch, compute ||e_k||^2, build transposed E
// ---------------------------------------------------------------------------
__global__ void prep_kernel(const float* __restrict__ emb) {
    int tid = blockIdx.x * blockDim.x + threadIdx.x;   // 262144 threads
    if (tid < K_ * D_) {
        g_dw[tid] = 0.0f;
        int k = tid & (K_ - 1);
        int d = tid >> 10;
        g_Et[tid] = emb[k * D_ + d];                   // Et[d*1024 + k]
    }
    if (tid < K_) {
        g_counts[tid] = 0.0f;
        const float* e = emb + tid * D_;
        float s = 0.0f;
        #pragma unroll 8
        for (int d = 0; d < D_; ++d) { float v = e[d]; s += v * v; }
        g_enorm[tid] = s;
    }
    if (tid == 0) g_loss = 0.0;
}

// ---------------------------------------------------------------------------
// Kernel 1: fused distance GEMM + argmin, fp32x2 packed-FMA inner loop.
// Block = 128 n-rows. 8 k-chunks of 128 codes; D streamed in 32-wide smem
// tiles; 8x8 register micro-tile per thread, accumulators packed pairwise
// along k (codes) into f32x2. Tie-break = lowest index (matches jnp.argmin).
// ---------------------------------------------------------------------------
__global__ void __launch_bounds__(256, 2)
dist_argmin_kernel(const float* __restrict__ z, float* __restrict__ out_idx_f) {
    __shared__ __align__(16) float Zs[32][128];
    __shared__ __align__(16) float Es[32][128];
    __shared__ float rmin[128];
    __shared__ int   ridx[128];

    const int tid = threadIdx.x;
    const int n0  = blockIdx.x * 128;
    const int b   = n0 >> 12;            // n0 / 4096
    const int hw0 = n0 & 4095;
    const float* zb = z + (size_t)b * D_ * HW_ + hw0;

    const int tk = tid & 15;             // 16 threads along k
    const int tn = tid >> 4;             // 16 thread-groups along n

    if (tid < 128) { rmin[tid] = 3.4e38f; ridx[tid] = 0; }

    const int w    = tid >> 5;           // warp id (0..7) for tile loads
    const int lane = tid & 31;

    for (int kc = 0; kc < 8; ++kc) {
        // acc[i][j2] holds codes (k0+tk*8+2*j2, +1) for row i, packed f32x2
        unsigned long long acc[8][4];
        #pragma unroll
        for (int i = 0; i < 8; ++i)
            #pragma unroll
            for (int j = 0; j < 4; ++j) acc[i][j] = 0ull;

        const int k0 = kc * 128;

        for (int dc = 0; dc < 8; ++dc) {
            __syncthreads();
            // Load Zs[32][128] and Es[32][128]; each warp loads 4 d-rows.
            #pragma unroll
            for (int r = 0; r < 4; ++r) {
                int dd = w * 4 + r;
                int d  = dc * 32 + dd;
                float4 zv = *(const float4*)(zb + (size_t)d * HW_ + lane * 4);
                *(float4*)&Zs[dd][lane * 4] = zv;
                float4 ev = *(const float4*)(g_Et + (size_t)d * K_ + k0 + lane * 4);
                *(float4*)&Es[dd][lane * 4] = ev;
            }
            __syncthreads();

            #pragma unroll
            for (int dd = 0; dd < 32; ++dd) {
                float4 a0 = *(float4*)&Zs[dd][tn * 8];
                float4 a1 = *(float4*)&Zs[dd][tn * 8 + 4];
                // Es pairs along k pack naturally (consecutive codes)
                ulonglong2 b0 = *(ulonglong2*)&Es[dd][tk * 8];
                ulonglong2 b1 = *(ulonglong2*)&Es[dd][tk * 8 + 4];
                unsigned long long bv[4] = {b0.x, b0.y, b1.x, b1.y};
                float av[8] = {a0.x, a0.y, a0.z, a0.w, a1.x, a1.y, a1.z, a1.w};
                #pragma unroll
                for (int i = 0; i < 8; ++i) {
                    unsigned long long a2;
                    PACK_F32X2F(a2, av[i], av[i]);
                    #pragma unroll
                    for (int j = 0; j < 4; ++j)
                        FMA_F32X2(acc[i][j], a2, bv[j], acc[i][j]);
                }
            }
        }

        // Epilogue for this k-chunk: score = ||e||^2 - 2*dot, running min.
        #pragma unroll
        for (int i = 0; i < 8; ++i) {
            float best = 3.4e38f; int bi = 0;
            #pragma unroll
            for (int j = 0; j < 4; ++j) {
                float dlo, dhi;
                UNPACK_F32X2F(dlo, dhi, acc[i][j]);
                int k = k0 + tk * 8 + j * 2;
                float s0 = g_enorm[k]     - 2.0f * dlo;
                float s1 = g_enorm[k + 1] - 2.0f * dhi;
                if (s0 < best) { best = s0; bi = k; }      // ascending k -> first min
                if (s1 < best) { best = s1; bi = k + 1; }
            }
            #pragma unroll
            for (int off = 8; off > 0; off >>= 1) {
                float ov = __shfl_down_sync(0xffffffffu, best, off, 16);
                int   oi = __shfl_down_sync(0xffffffffu, bi,   off, 16);
                if (ov < best || (ov == best && oi < bi)) { best = ov; bi = oi; }
            }
            if (tk == 0) {
                int ln = tn * 8 + i;                   // owned exclusively by this thread
                if (best < rmin[ln]) { rmin[ln] = best; ridx[ln] = bi; }
            }
        }
    }
    __syncthreads();

    if (tid < 128) {
        int n = n0 + tid;
        int idx = ridx[tid];
        g_idx[n] = idx;
        out_idx_f[n] = (float)idx;
        atomicAdd(&g_counts[idx], 1.0f);
    }
}

// ---------------------------------------------------------------------------
// Kernel 2: gather quantized, accumulate commitment-loss sum, scatter dw.
// One thread per z element (b,d,hw) with hw fastest -> coalesced z/out.
// ---------------------------------------------------------------------------
__global__ void gather_loss_dw_kernel(const float* __restrict__ z,
                                      const float* __restrict__ emb,
                                      float* __restrict__ out_q) {
    int e  = blockIdx.x * 256 + threadIdx.x;   // [0, 33554432)
    int hw = e & 4095;
    int bd = e >> 12;
    int d  = bd & 255;
    int b  = bd >> 8;
    int n  = (b << 12) | hw;

    int   idx = g_idx[n];
    float q   = emb[idx * D_ + d];
    float zv  = z[e];
    out_q[e]  = q;
    float diff = zv - q;
    float sq   = diff * diff;
    atomicAdd(&g_dw[idx * D_ + d], zv);

    // block reduction of sq
    #pragma unroll
    for (int off = 16; off > 0; off >>= 1)
        sq += __shfl_down_sync(0xffffffffu, sq, off);
    __shared__ float wsum[8];
    int lane = threadIdx.x & 31, wid = threadIdx.x >> 5;
    if (lane == 0) wsum[wid] = sq;
    __syncthreads();
    if (wid == 0) {
        float v = (lane < 8) ? wsum[lane] : 0.0f;
        #pragma unroll
        for (int off = 4; off > 0; off >>= 1)
            v += __shfl_down_sync(0xffffffffu, v, off);
        if (lane == 0) atomicAdd(&g_loss, (double)v);
    }
}

// ---------------------------------------------------------------------------
// Kernel 3: EMA updates + loss finalize
// ---------------------------------------------------------------------------
__global__ void finalize_kernel(const float* __restrict__ ema_cs,
                                const float* __restrict__ ema_emb,
                                float* __restrict__ out) {
    int i = blockIdx.x * 256 + threadIdx.x;    // 262144 threads
    const float decay = 0.99f;
    const float omd   = (float)(1.0 - 0.99);   // matches Python (1.0 - DECAY) -> f32
    if (i < K_ * D_) out[OUT_EMB + i] = decay * ema_emb[i] + omd * g_dw[i];
    if (i < K_)      out[OUT_CS  + i] = decay * ema_cs[i]  + omd * g_counts[i];
    if (i == 0)      out[OUT_LOSS]    = 0.25f * (float)(g_loss / (double)TOTQ);
}

// ---------------------------------------------------------------------------
extern "C" void kernel_launch(void* const* d_in, const int* in_sizes, int n_in,
                              void* d_out, int out_size) {
    const float* z       = (const float*)d_in[0];
    const float* emb     = (const float*)d_in[1];
    const float* ema_cs  = (const float*)d_in[2];
    const float* ema_emb = (const float*)d_in[3];
    float* out = (float*)d_out;

    prep_kernel<<<1024, 256>>>(emb);
    dist_argmin_kernel<<<N_ / 128, 256>>>(z, out + OUT_IDX);
    gather_loss_dw_kernel<<<TOTQ / 256, 256>>>(z, emb, out);
    finalize_kernel<<<1024, 256>>>(ema_cs, ema_emb, out);
}

// round 5
// speedup vs baseline: 1.0305x; 1.0010x over previous
#include <cuda_runtime.h>

#define B_   32
#define D_   256
#define HW_  4096
#define N_   131072          // B*H*W
#define K_   1024
#define TOTQ 33554432        // B*D*H*W

// Output layout (flattened tuple, float32):
//   [0, 33554432)                quantized_ste
//   [33554432]                   commitment_loss
//   [33554433, 33685505)         encoding_indices (as float)
//   [33685505, 33686529)         new_cluster_size
//   [33686529, 33948673)         new_ema_embedding
#define OUT_LOSS 33554432
#define OUT_IDX  33554433
#define OUT_CS   33685505
#define OUT_EMB  33686529

// Device scratch (no allocations allowed)
__device__ float  g_Et[D_ * K_];     // E transposed, d-major: Et[d*K + k]
__device__ float  g_enorm[K_];
__device__ int    g_idx[N_];
__device__ float  g_counts[K_];
__device__ float  g_dw[K_ * D_];
__device__ double g_loss;

// Packed fp32x2 FMA (sm_103a): 2 FMAs/instruction, fma.rn per lane (bit-exact).
#define FMA_F32X2(d, a, b, c) \
    asm("fma.rn.f32x2 %0, %1, %2, %3;" : "=l"(d) : "l"(a), "l"(b), "l"(c))
#define PACK_F32X2F(out, lo, hi) \
    asm("mov.b64 %0, {%1, %2};" : "=l"(out) : "f"(lo), "f"(hi))
#define UNPACK_F32X2F(lo, hi, in) \
    asm("mov.b64 {%0, %1}, %2;" : "=f"(lo), "=f"(hi) : "l"(in))

// ---------------------------------------------------------------------------
// Kernel 0: zero scratch, compute ||e_k||^2, build transposed E
// ---------------------------------------------------------------------------
__global__ void prep_kernel(const float* __restrict__ emb) {
    int tid = blockIdx.x * blockDim.x + threadIdx.x;   // 262144 threads
    if (tid < K_ * D_) {
        g_dw[tid] = 0.0f;
        int k = tid & (K_ - 1);
        int d = tid >> 10;
        g_Et[tid] = emb[k * D_ + d];                   // Et[d*1024 + k]
    }
    if (tid < K_) {
        g_counts[tid] = 0.0f;
        const float* e = emb + tid * D_;
        float s = 0.0f;
        #pragma unroll 8
        for (int d = 0; d < D_; ++d) { float v = e[d]; s += v * v; }
        g_enorm[tid] = s;
    }
    if (tid == 0) g_loss = 0.0;
}

// ---------------------------------------------------------------------------
// Kernel 1: fused distance GEMM + argmin, fp32x2 packed-FMA inner loop.
// Block = 128 n-rows. 8 k-chunks of 128 codes; D streamed in 32-wide smem
// tiles; 8x8 register micro-tile per thread, accumulators packed pairwise
// along k (codes) into f32x2. Tie-break = lowest index (matches jnp.argmin).
// ---------------------------------------------------------------------------
__global__ void __launch_bounds__(256, 2)
dist_argmin_kernel(const float* __restrict__ z, float* __restrict__ out_idx_f) {
    __shared__ __align__(16) float Zs[32][128];
    __shared__ __align__(16) float Es[32][128];
    __shared__ float rmin[128];
    __shared__ int   ridx[128];

    const int tid = threadIdx.x;
    const int n0  = blockIdx.x * 128;
    const int b   = n0 >> 12;            // n0 / 4096
    const int hw0 = n0 & 4095;
    const float* zb = z + (size_t)b * D_ * HW_ + hw0;

    const int tk = tid & 15;             // 16 threads along k
    const int tn = tid >> 4;             // 16 thread-groups along n

    if (tid < 128) { rmin[tid] = 3.4e38f; ridx[tid] = 0; }

    const int w    = tid >> 5;           // warp id (0..7) for tile loads
    const int lane = tid & 31;

    for (int kc = 0; kc < 8; ++kc) {
        // acc[i][j2] holds codes (k0+tk*8+2*j2, +1) for row i, packed f32x2
        unsigned long long acc[8][4];
        #pragma unroll
        for (int i = 0; i < 8; ++i)
            #pragma unroll
            for (int j = 0; j < 4; ++j) acc[i][j] = 0ull;

        const int k0 = kc * 128;

        for (int dc = 0; dc < 8; ++dc) {
            __syncthreads();
            // Load Zs[32][128] and Es[32][128]; each warp loads 4 d-rows.
            #pragma unroll
            for (int r = 0; r < 4; ++r) {
                int dd = w * 4 + r;
                int d  = dc * 32 + dd;
                float4 zv = *(const float4*)(zb + (size_t)d * HW_ + lane * 4);
                *(float4*)&Zs[dd][lane * 4] = zv;
                float4 ev = *(const float4*)(g_Et + (size_t)d * K_ + k0 + lane * 4);
                *(float4*)&Es[dd][lane * 4] = ev;
            }
            __syncthreads();

            #pragma unroll
            for (int dd = 0; dd < 32; ++dd) {
                float4 a0 = *(float4*)&Zs[dd][tn * 8];
                float4 a1 = *(float4*)&Zs[dd][tn * 8 + 4];
                // Es pairs along k pack naturally (consecutive codes)
                ulonglong2 b0 = *(ulonglong2*)&Es[dd][tk * 8];
                ulonglong2 b1 = *(ulonglong2*)&Es[dd][tk * 8 + 4];
                unsigned long long bv[4] = {b0.x, b0.y, b1.x, b1.y};
                float av[8] = {a0.x, a0.y, a0.z, a0.w, a1.x, a1.y, a1.z, a1.w};
                #pragma unroll
                for (int i = 0; i < 8; ++i) {
                    unsigned long long a2;
                    PACK_F32X2F(a2, av[i], av[i]);
                    #pragma unroll
                    for (int j = 0; j < 4; ++j)
                        FMA_F32X2(acc[i][j], a2, bv[j], acc[i][j]);
                }
            }
        }

        // Epilogue for this k-chunk: score = ||e||^2 - 2*dot, running min.
        #pragma unroll
        for (int i = 0; i < 8; ++i) {
            float best = 3.4e38f; int bi = 0;
            #pragma unroll
            for (int j = 0; j < 4; ++j) {
                float dlo, dhi;
                UNPACK_F32X2F(dlo, dhi, acc[i][j]);
                int k = k0 + tk * 8 + j * 2;
                float s0 = g_enorm[k]     - 2.0f * dlo;
                float s1 = g_enorm[k + 1] - 2.0f * dhi;
                if (s0 < best) { best = s0; bi = k; }      // ascending k -> first min
                if (s1 < best) { best = s1; bi = k + 1; }
            }
            #pragma unroll
            for (int off = 8; off > 0; off >>= 1) {
                float ov = __shfl_down_sync(0xffffffffu, best, off, 16);
                int   oi = __shfl_down_sync(0xffffffffu, bi,   off, 16);
                if (ov < best || (ov == best && oi < bi)) { best = ov; bi = oi; }
            }
            if (tk == 0) {
                int ln = tn * 8 + i;                   // owned exclusively by this thread
                if (best < rmin[ln]) { rmin[ln] = best; ridx[ln] = bi; }
            }
        }
    }
    __syncthreads();

    if (tid < 128) {
        int n = n0 + tid;
        int idx = ridx[tid];
        g_idx[n] = idx;
        out_idx_f[n] = (float)idx;
        atomicAdd(&g_counts[idx], 1.0f);
    }
}

// ---------------------------------------------------------------------------
// Kernel 2: gather quantized, accumulate commitment-loss sum, scatter dw.
// One thread per z element (b,d,hw) with hw fastest -> coalesced z/out.
// ---------------------------------------------------------------------------
__global__ void gather_loss_dw_kernel(const float* __restrict__ z,
                                      const float* __restrict__ emb,
                                      float* __restrict__ out_q) {
    int e  = blockIdx.x * 256 + threadIdx.x;   // [0, 33554432)
    int hw = e & 4095;
    int bd = e >> 12;
    int d  = bd & 255;
    int b  = bd >> 8;
    int n  = (b << 12) | hw;

    int   idx = g_idx[n];
    float q   = emb[idx * D_ + d];
    float zv  = z[e];
    out_q[e]  = q;
    float diff = zv - q;
    float sq   = diff * diff;
    atomicAdd(&g_dw[idx * D_ + d], zv);

    // block reduction of sq
    #pragma unroll
    for (int off = 16; off > 0; off >>= 1)
        sq += __shfl_down_sync(0xffffffffu, sq, off);
    __shared__ float wsum[8];
    int lane = threadIdx.x & 31, wid = threadIdx.x >> 5;
    if (lane == 0) wsum[wid] = sq;
    __syncthreads();
    if (wid == 0) {
        float v = (lane < 8) ? wsum[lane] : 0.0f;
        #pragma unroll
        for (int off = 4; off > 0; off >>= 1)
            v += __shfl_down_sync(0xffffffffu, v, off);
        if (lane == 0) atomicAdd(&g_loss, (double)v);
    }
}

// ---------------------------------------------------------------------------
// Kernel 3: EMA updates + loss finalize
// ---------------------------------------------------------------------------
__global__ void finalize_kernel(const float* __restrict__ ema_cs,
                                const float* __restrict__ ema_emb,
                                float* __restrict__ out) {
    int i = blockIdx.x * 256 + threadIdx.x;    // 262144 threads
    const float decay = 0.99f;
    const float omd   = (float)(1.0 - 0.99);   // matches Python (1.0 - DECAY) -> f32
    if (i < K_ * D_) out[OUT_EMB + i] = decay * ema_emb[i] + omd * g_dw[i];
    if (i < K_)      out[OUT_CS  + i] = decay * ema_cs[i]  + omd * g_counts[i];
    if (i == 0)      out[OUT_LOSS]    = 0.25f * (float)(g_loss / (double)TOTQ);
}

// ---------------------------------------------------------------------------
extern "C" void kernel_launch(void* const* d_in, const int* in_sizes, int n_in,
                              void* d_out, int out_size) {
    const float* z       = (const float*)d_in[0];
    const float* emb     = (const float*)d_in[1];
    const float* ema_cs  = (const float*)d_in[2];
    const float* ema_emb = (const float*)d_in[3];
    float* out = (float*)d_out;

    prep_kernel<<<1024, 256>>>(emb);
    dist_argmin_kernel<<<N_ / 128, 256>>>(z, out + OUT_IDX);
    gather_loss_dw_kernel<<<TOTQ / 256, 256>>>(z, emb, out);
    finalize_kernel<<<1024, 256>>>(ema_cs, ema_emb, out);
}

// round 7
// speedup vs baseline: 1.3158x; 1.2769x over previous
#include <cuda_runtime.h>
#include <cstdint>

#define B_   32
#define D_   256
#define HW_  4096
#define N_   131072
#define K_   1024
#define TOTQ 33554432

#define OUT_LOSS 33554432
#define OUT_IDX  33554433
#define OUT_CS   33685505
#define OUT_EMB  33686529

#define GAP_TH 0.5f

__device__ float  g_enorm[K_];
__device__ int    g_idx[N_];
__device__ float  g_counts[K_];
__device__ float  g_dw[K_ * D_];
__device__ double g_loss;
__device__ int    g_flag_cnt;
__device__ int    g_fr_n[N_];
__device__ int    g_fr_c[N_];

// smem layout (bytes): A 128 rows x 272 floats (k-interleaved, padded),
// B 2 x (128 codes x 48 floats), enorm 1024 floats.
#define A_STRIDE   272
#define B_STRIDE   48
#define A_BYTES    139264                 // 128*272*4
#define B_OFF(i)   (A_BYTES + (i) * 24576)
#define EN_OFF     (A_BYTES + 49152)      // 188416
#define SMEM_TOTAL (EN_OFF + 4096)        // 192512

// interleaved position of d within its group of 16: [0,4,8,12,1,5,9,13,2,6,10,14,3,7,11,15]
__device__ __forceinline__ int permoff(int d) {
    return ((d >> 4) << 4) + ((d & 3) << 2) + ((d & 15) >> 2);
}

#define MMA_TF32(c0, c1, c2, c3, a0, a1, a2, a3, b0, b1)                     \
    asm volatile("mma.sync.aligned.m16n8k8.row.col.f32.tf32.tf32.f32 "       \
        "{%0,%1,%2,%3}, {%4,%5,%6,%7}, {%8,%9}, {%0,%1,%2,%3};"              \
        : "+f"(c0), "+f"(c1), "+f"(c2), "+f"(c3)                             \
        : "r"(a0), "r"(a1), "r"(a2), "r"(a3), "r"(b0), "r"(b1))

// ---------------------------------------------------------------------------
// Kernel 0: zero scratch + exact ||e_k||^2
// ---------------------------------------------------------------------------
__global__ void prep_kernel(const float* __restrict__ emb) {
    int tid = blockIdx.x * blockDim.x + threadIdx.x;   // 262144 threads
    if (tid < K_ * D_) g_dw[tid] = 0.0f;
    if (tid < K_) {
        g_counts[tid] = 0.0f;
        const float* e = emb + tid * D_;
        float s = 0.0f;
        #pragma unroll 8
        for (int d = 0; d < D_; ++d) { float v = e[d]; s += v * v; }
        g_enorm[tid] = s;
    }
    if (tid == 0) { g_loss = 0.0; g_flag_cnt = 0; }
}

// ---------------------------------------------------------------------------
// Kernel 1: TF32 mma.sync distance GEMM + fused argmin (top-2/thread,
// merged to top-3/row). Rows with small tf32 gap flagged for exact recheck.
// ---------------------------------------------------------------------------
__global__ void __launch_bounds__(256, 1)
mma_argmin_kernel(const float* __restrict__ z, const float* __restrict__ emb,
                  float* __restrict__ out_idx_f) {
    extern __shared__ __align__(16) char smem_[];
    float* As = (float*)smem_;
    float* en = (float*)(smem_ + EN_OFF);

    const int tid  = threadIdx.x;
    const int lane = tid & 31;
    const int wid  = tid >> 5;
    const int g    = lane >> 2;          // fragment group
    const int t    = lane & 3;           // thread-in-group
    const int mw   = wid >> 1;           // warp m index (0..3)
    const int nw   = wid & 1;            // warp n index (0..1)
    const int m0   = mw * 32;
    const int n0w  = nw * 64;

    const int n0  = blockIdx.x * 128;
    const int bb  = n0 >> 12;
    const int hw0 = n0 & 4095;
    const float* zb = z + (size_t)bb * (D_ * HW_) + hw0;

    // ---- A load: 128 rows x 256 d, interleaved layout ----
    {
        const int arow = tid & 127;
        const int ah   = tid >> 7;
        #pragma unroll 4
        for (int k = 0; k < 128; ++k) {
            int d = ah * 128 + k;
            As[arow * A_STRIDE + permoff(d)] = zb[(size_t)d * HW_ + arow];
        }
    }
    // ---- enorm -> smem ----
    #pragma unroll
    for (int i = 0; i < 4; ++i) en[tid + 256 * i] = g_enorm[tid + 256 * i];

    // ---- B tile loader lambda-ish (code tid>>1, half tid&1) ----
    const int bc  = tid >> 1;
    const int seg = tid & 1;
    float4 pf[4];
    {   // prologue: tile 0 (cc=0, dc=0)
        const float4* src = (const float4*)(emb + (size_t)bc * 256 + seg * 16);
        #pragma unroll
        for (int i = 0; i < 4; ++i) pf[i] = src[i];
        float* Bp = (float*)(smem_ + B_OFF(0));
        #pragma unroll
        for (int i = 0; i < 4; ++i) {
            const float* e4 = (const float*)&pf[i];
            #pragma unroll
            for (int j = 0; j < 4; ++j)
                Bp[bc * B_STRIDE + seg * 16 + j * 4 + i] = e4[j];
        }
    }
    __syncthreads();

    float acc[2][8][4];
    float s1[4], s2[4];
    int   i1[4], i2[4];
    #pragma unroll
    for (int r = 0; r < 4; ++r) { s1[r] = 3.4e38f; s2[r] = 3.4e38f; i1[r] = 0; i2[r] = 0; }
    #pragma unroll
    for (int a = 0; a < 2; ++a)
        #pragma unroll
        for (int b = 0; b < 8; ++b)
            #pragma unroll
            for (int c = 0; c < 4; ++c) acc[a][b][c] = 0.0f;

    for (int tile = 0; tile < 64; ++tile) {
        const int dc = tile & 7;
        // prefetch next tile from gmem
        if (tile < 63) {
            int nt = tile + 1;
            const float4* src = (const float4*)(emb
                + (size_t)((nt >> 3) * 128 + bc) * 256 + (nt & 7) * 32 + seg * 16);
            #pragma unroll
            for (int i = 0; i < 4; ++i) pf[i] = src[i];
        }
        // compute current tile: 4 k-steps (2 interleave groups x 2)
        const float* Bp = (const float*)(smem_ + B_OFF(tile & 1));
        #pragma unroll
        for (int p = 0; p < 2; ++p) {
            const int goff = (dc * 2 + p) * 16 + t * 4;     // float offset in A row
            float4 Af[2][2];
            #pragma unroll
            for (int mb = 0; mb < 2; ++mb) {
                int r0 = m0 + mb * 16 + g;
                Af[mb][0] = *(const float4*)(As + r0 * A_STRIDE + goff);
                Af[mb][1] = *(const float4*)(As + (r0 + 8) * A_STRIDE + goff);
            }
            #pragma unroll
            for (int nb = 0; nb < 8; ++nb) {
                int cr = n0w + nb * 8 + g;
                float4 Bf = *(const float4*)(Bp + cr * B_STRIDE + p * 16 + t * 4);
                #pragma unroll
                for (int mb = 0; mb < 2; ++mb) {
                    MMA_TF32(acc[mb][nb][0], acc[mb][nb][1], acc[mb][nb][2], acc[mb][nb][3],
                             __float_as_uint(Af[mb][0].x), __float_as_uint(Af[mb][1].x),
                             __float_as_uint(Af[mb][0].y), __float_as_uint(Af[mb][1].y),
                             __float_as_uint(Bf.x), __float_as_uint(Bf.y));
                    MMA_TF32(acc[mb][nb][0], acc[mb][nb][1], acc[mb][nb][2], acc[mb][nb][3],
                             __float_as_uint(Af[mb][0].z), __float_as_uint(Af[mb][1].z),
                             __float_as_uint(Af[mb][0].w), __float_as_uint(Af[mb][1].w),
                             __float_as_uint(Bf.z), __float_as_uint(Bf.w));
                }
            }
        }
        // store prefetched tile into the other buffer
        if (tile < 63) {
            float* Bn = (float*)(smem_ + B_OFF((tile + 1) & 1));
            #pragma unroll
            for (int i = 0; i < 4; ++i) {
                const float* e4 = (const float*)&pf[i];
                #pragma unroll
                for (int j = 0; j < 4; ++j)
                    Bn[bc * B_STRIDE + seg * 16 + j * 4 + i] = e4[j];
            }
        }
        // epilogue at the end of each code-chunk
        if (dc == 7) {
            const int cc = tile >> 3;
            #pragma unroll
            for (int mb = 0; mb < 2; ++mb) {
                #pragma unroll
                for (int h = 0; h < 2; ++h) {
                    const int r4 = mb * 2 + h;
                    #pragma unroll
                    for (int nb = 0; nb < 8; ++nb) {
                        int c0 = cc * 128 + n0w + nb * 8 + 2 * t;
                        float sc0 = fmaf(-2.0f, acc[mb][nb][h * 2 + 0], en[c0]);
                        float sc1 = fmaf(-2.0f, acc[mb][nb][h * 2 + 1], en[c0 + 1]);
                        if (sc0 < s1[r4]) { s2[r4] = s1[r4]; i2[r4] = i1[r4]; s1[r4] = sc0; i1[r4] = c0; }
                        else if (sc0 < s2[r4]) { s2[r4] = sc0; i2[r4] = c0; }
                        if (sc1 < s1[r4]) { s2[r4] = s1[r4]; i2[r4] = i1[r4]; s1[r4] = sc1; i1[r4] = c0 + 1; }
                        else if (sc1 < s2[r4]) { s2[r4] = sc1; i2[r4] = c0 + 1; }
                    }
                }
            }
            #pragma unroll
            for (int a = 0; a < 2; ++a)
                #pragma unroll
                for (int b = 0; b < 8; ++b)
                    #pragma unroll
                    for (int c = 0; c < 4; ++c) acc[a][b][c] = 0.0f;
        }
        __syncthreads();
    }

    // ---- merge per-row candidates (8 owner threads x top-2) via smem ----
    float2* ms = (float2*)smem_;             // reuse A region
    int2*   mi = (int2*)(smem_ + 16384);
    const int slot = nw * 4 + t;
    #pragma unroll
    for (int r4 = 0; r4 < 4; ++r4) {
        int row = m0 + (r4 >> 1) * 16 + (r4 & 1) * 8 + g;
        ms[row * 8 + slot] = make_float2(s1[r4], s2[r4]);
        mi[row * 8 + slot] = make_int2(i1[r4], i2[r4]);
    }
    __syncthreads();

    if (tid < 128) {
        float b1 = 3.4e38f, b2 = 3.4e38f, b3 = 3.4e38f;
        int   j1 = 0, j2 = 0, j3 = 0;
        #pragma unroll
        for (int s = 0; s < 8; ++s) {
            float2 sv = ms[tid * 8 + s];
            int2   iv = mi[tid * 8 + s];
            float cs[2] = { sv.x, sv.y };
            int   ci[2] = { iv.x, iv.y };
            #pragma unroll
            for (int q = 0; q < 2; ++q) {
                float sc = cs[q]; int k = ci[q];
                if (sc < b1 || (sc == b1 && k < j1)) {
                    b3 = b2; j3 = j2; b2 = b1; j2 = j1; b1 = sc; j1 = k;
                } else if (sc < b2 || (sc == b2 && k < j2)) {
                    b3 = b2; j3 = j2; b2 = sc; j2 = k;
                } else if (sc < b3 || (sc == b3 && k < j3)) {
                    b3 = sc; j3 = k;
                }
            }
        }
        const int n = n0 + tid;
        if (b2 - b1 < GAP_TH) {
            int pos = atomicAdd(&g_flag_cnt, 1);
            int pk = j1 | (j2 << 10) | (j3 << 20) | ((b3 - b1 < GAP_TH) ? (1 << 30) : 0);
            g_fr_n[pos] = n;
            g_fr_c[pos] = pk;
        } else {
            g_idx[n] = j1;
            out_idx_f[n] = (float)j1;
        }
    }
}

// ---------------------------------------------------------------------------
// Kernel 1b: exact fp32 re-rank of flagged rows (one warp per row).
// ---------------------------------------------------------------------------
__global__ void __launch_bounds__(256)
recheck_kernel(const float* __restrict__ z, const float* __restrict__ emb,
               float* __restrict__ out_idx_f) {
    const int gw   = (blockIdx.x * 256 + threadIdx.x) >> 5;
    const int lane = threadIdx.x & 31;
    const int nwarp = gridDim.x * 8;
    const int cnt = g_flag_cnt;

    for (int f = gw; f < cnt; f += nwarp) {
        int n  = g_fr_n[f];
        int pk = g_fr_c[f];
        int cand[3];
        cand[0] = pk & 1023;
        cand[1] = (pk >> 10) & 1023;
        cand[2] = (pk >> 20) & 1023;
        int nc = (pk >> 30) ? 3 : 2;

        int b = n >> 12, hw = n & 4095;
        const float* zr = z + (size_t)b * (D_ * HW_) + hw;
        float zv[8];
        #pragma unroll
        for (int i = 0; i < 8; ++i) zv[i] = zr[(size_t)(lane + 32 * i) * HW_];

        float bs = 3.4e38f; int bi = 0;
        for (int q = 0; q < nc; ++q) {
            int cc = cand[q];
            const float* e = emb + cc * D_;
            float p = 0.0f;
            #pragma unroll
            for (int i = 0; i < 8; ++i) p = fmaf(zv[i], e[lane + 32 * i], p);
            #pragma unroll
            for (int off = 16; off > 0; off >>= 1)
                p += __shfl_down_sync(0xffffffffu, p, off);
            if (lane == 0) {
                float s = g_enorm[cc] - 2.0f * p;
                if (s < bs || (s == bs && cc < bi)) { bs = s; bi = cc; }
            }
        }
        if (lane == 0) { g_idx[n] = bi; out_idx_f[n] = (float)bi; }
    }
}

// ---------------------------------------------------------------------------
// Kernel 2: gather quantized, loss sum, dw scatter, counts (at d==0).
// ---------------------------------------------------------------------------
__global__ void gather_loss_dw_kernel(const float* __restrict__ z,
                                      const float* __restrict__ emb,
                                      float* __restrict__ out_q) {
    int e  = blockIdx.x * 256 + threadIdx.x;
    int hw = e & 4095;
    int bd = e >> 12;
    int d  = bd & 255;
    int b  = bd >> 8;
    int n  = (b << 12) | hw;

    int   idx = g_idx[n];
    float q   = emb[idx * D_ + d];
    float zv  = z[e];
    out_q[e]  = q;
    float diff = zv - q;
    float sq   = diff * diff;
    atomicAdd(&g_dw[idx * D_ + d], zv);
    if (d == 0) atomicAdd(&g_counts[idx], 1.0f);

    #pragma unroll
    for (int off = 16; off > 0; off >>= 1)
        sq += __shfl_down_sync(0xffffffffu, sq, off);
    __shared__ float wsum[8];
    int lane = threadIdx.x & 31, wid = threadIdx.x >> 5;
    if (lane == 0) wsum[wid] = sq;
    __syncthreads();
    if (wid == 0) {
        float v = (lane < 8) ? wsum[lane] : 0.0f;
        #pragma unroll
        for (int off = 4; off > 0; off >>= 1)
            v += __shfl_down_sync(0xffffffffu, v, off);
        if (lane == 0) atomicAdd(&g_loss, (double)v);
    }
}

// ---------------------------------------------------------------------------
// Kernel 3: EMA updates + loss finalize
// ---------------------------------------------------------------------------
__global__ void finalize_kernel(const float* __restrict__ ema_cs,
                                const float* __restrict__ ema_emb,
                                float* __restrict__ out) {
    int i = blockIdx.x * 256 + threadIdx.x;
    const float decay = 0.99f;
    const float omd   = (float)(1.0 - 0.99);
    if (i < K_ * D_) out[OUT_EMB + i] = decay * ema_emb[i] + omd * g_dw[i];
    if (i < K_)      out[OUT_CS  + i] = decay * ema_cs[i]  + omd * g_counts[i];
    if (i == 0)      out[OUT_LOSS]    = 0.25f * (float)(g_loss / (double)TOTQ);
}

// ---------------------------------------------------------------------------
extern "C" void kernel_launch(void* const* d_in, const int* in_sizes, int n_in,
                              void* d_out, int out_size) {
    const float* z       = (const float*)d_in[0];
    const float* emb     = (const float*)d_in[1];
    const float* ema_cs  = (const float*)d_in[2];
    const float* ema_emb = (const float*)d_in[3];
    float* out = (float*)d_out;

    static int smem_set = 0;
    if (!smem_set) {
        cudaFuncSetAttribute(mma_argmin_kernel,
                             cudaFuncAttributeMaxDynamicSharedMemorySize, SMEM_TOTAL);
        smem_set = 1;
    }

    prep_kernel<<<1024, 256>>>(emb);
    mma_argmin_kernel<<<N_ / 128, 256, SMEM_TOTAL>>>(z, emb, out + OUT_IDX);
    recheck_kernel<<<256, 256>>>(z, emb, out + OUT_IDX);
    gather_loss_dw_kernel<<<TOTQ / 256, 256>>>(z, emb, out);
    finalize_kernel<<<1024, 256>>>(ema_cs, ema_emb, out);
}

// round 8
// speedup vs baseline: 1.9970x; 1.5177x over previous
#include <cuda_runtime.h>
#include <cstdint>

#define B_   32
#define D_   256
#define HW_  4096
#define N_   131072
#define K_   1024
#define TOTQ 33554432

#define OUT_LOSS 33554432
#define OUT_IDX  33554433
#define OUT_CS   33685505
#define OUT_EMB  33686529

#define GAP_TH 0.5f

__device__ float  g_enorm[K_];
__device__ int    g_idx[N_];
__device__ float  g_counts[K_];
__device__ float  g_dw[K_ * D_];
__device__ double g_loss;
__device__ int    g_flag_cnt;
__device__ int    g_fr_n[N_];
__device__ int    g_fr_c[N_];

// smem layout (bytes): A 128 rows x 272 floats (k-interleaved, padded),
// B 2 x (128 codes x 48 floats), enorm 1024 floats.
#define A_STRIDE   272
#define B_STRIDE   48
#define A_BYTES    139264                 // 128*272*4
#define B_OFF(i)   (A_BYTES + (i) * 24576)
#define EN_OFF     (A_BYTES + 49152)      // 188416
#define SMEM_TOTAL (EN_OFF + 4096)        // 192512

// interleaved position of d within its group of 16: [0,4,8,12,1,5,9,13,2,6,10,14,3,7,11,15]
__device__ __forceinline__ int permoff(int d) {
    return ((d >> 4) << 4) + ((d & 3) << 2) + ((d & 15) >> 2);
}

#define MMA_TF32(c0, c1, c2, c3, a0, a1, a2, a3, b0, b1)                     \
    asm volatile("mma.sync.aligned.m16n8k8.row.col.f32.tf32.tf32.f32 "       \
        "{%0,%1,%2,%3}, {%4,%5,%6,%7}, {%8,%9}, {%0,%1,%2,%3};"              \
        : "+f"(c0), "+f"(c1), "+f"(c2), "+f"(c3)                             \
        : "r"(a0), "r"(a1), "r"(a2), "r"(a3), "r"(b0), "r"(b1))

// ---------------------------------------------------------------------------
// Kernel 0: zero scratch + exact ||e_k||^2
// ---------------------------------------------------------------------------
__global__ void prep_kernel(const float* __restrict__ emb) {
    int tid = blockIdx.x * blockDim.x + threadIdx.x;   // 262144 threads
    if (tid < K_ * D_) g_dw[tid] = 0.0f;
    if (tid < K_) {
        g_counts[tid] = 0.0f;
        const float* e = emb + tid * D_;
        float s = 0.0f;
        #pragma unroll 8
        for (int d = 0; d < D_; ++d) { float v = e[d]; s += v * v; }
        g_enorm[tid] = s;
    }
    if (tid == 0) { g_loss = 0.0; g_flag_cnt = 0; }
}

// ---------------------------------------------------------------------------
// Kernel 1: TF32 mma.sync distance GEMM + fused argmin (top-2/thread,
// merged to top-3/row). Rows with small tf32 gap flagged for exact recheck.
// ---------------------------------------------------------------------------
__global__ void __launch_bounds__(256, 1)
mma_argmin_kernel(const float* __restrict__ z, const float* __restrict__ emb,
                  float* __restrict__ out_idx_f) {
    extern __shared__ __align__(16) char smem_[];
    float* As = (float*)smem_;
    float* en = (float*)(smem_ + EN_OFF);

    const int tid  = threadIdx.x;
    const int lane = tid & 31;
    const int wid  = tid >> 5;
    const int g    = lane >> 2;          // fragment group
    const int t    = lane & 3;           // thread-in-group
    const int mw   = wid >> 1;           // warp m index (0..3)
    const int nw   = wid & 1;            // warp n index (0..1)
    const int m0   = mw * 32;
    const int n0w  = nw * 64;

    const int n0  = blockIdx.x * 128;
    const int bb  = n0 >> 12;
    const int hw0 = n0 & 4095;
    const float* zb = z + (size_t)bb * (D_ * HW_) + hw0;

    // ---- A load: 128 rows x 256 d, interleaved layout ----
    {
        const int arow = tid & 127;
        const int ah   = tid >> 7;
        #pragma unroll 4
        for (int k = 0; k < 128; ++k) {
            int d = ah * 128 + k;
            As[arow * A_STRIDE + permoff(d)] = zb[(size_t)d * HW_ + arow];
        }
    }
    // ---- enorm -> smem ----
    #pragma unroll
    for (int i = 0; i < 4; ++i) en[tid + 256 * i] = g_enorm[tid + 256 * i];

    // ---- B tile loader (code tid>>1, half tid&1) ----
    const int bc  = tid >> 1;
    const int seg = tid & 1;
    float4 pf[4];
    {   // prologue: tile 0 (cc=0, dc=0)
        const float4* src = (const float4*)(emb + (size_t)bc * 256 + seg * 16);
        #pragma unroll
        for (int i = 0; i < 4; ++i) pf[i] = src[i];
        float* Bp = (float*)(smem_ + B_OFF(0));
        #pragma unroll
        for (int i = 0; i < 4; ++i) {
            const float* e4 = (const float*)&pf[i];
            #pragma unroll
            for (int j = 0; j < 4; ++j)
                Bp[bc * B_STRIDE + seg * 16 + j * 4 + i] = e4[j];
        }
    }
    __syncthreads();

    float acc[2][8][4];
    float s1[4], s2[4];
    int   i1[4], i2[4];
    #pragma unroll
    for (int r = 0; r < 4; ++r) { s1[r] = 3.4e38f; s2[r] = 3.4e38f; i1[r] = 0; i2[r] = 0; }
    #pragma unroll
    for (int a = 0; a < 2; ++a)
        #pragma unroll
        for (int b = 0; b < 8; ++b)
            #pragma unroll
            for (int c = 0; c < 4; ++c) acc[a][b][c] = 0.0f;

    for (int tile = 0; tile < 64; ++tile) {
        const int dc = tile & 7;
        // prefetch next tile from gmem
        if (tile < 63) {
            int nt = tile + 1;
            const float4* src = (const float4*)(emb
                + (size_t)((nt >> 3) * 128 + bc) * 256 + (nt & 7) * 32 + seg * 16);
            #pragma unroll
            for (int i = 0; i < 4; ++i) pf[i] = src[i];
        }
        // compute current tile: 4 k-steps (2 interleave groups x 2)
        const float* Bp = (const float*)(smem_ + B_OFF(tile & 1));
        #pragma unroll
        for (int p = 0; p < 2; ++p) {
            const int goff = (dc * 2 + p) * 16 + t * 4;     // float offset in A row
            float4 Af[2][2];
            #pragma unroll
            for (int mb = 0; mb < 2; ++mb) {
                int r0 = m0 + mb * 16 + g;
                Af[mb][0] = *(const float4*)(As + r0 * A_STRIDE + goff);
                Af[mb][1] = *(const float4*)(As + (r0 + 8) * A_STRIDE + goff);
            }
            #pragma unroll
            for (int nb = 0; nb < 8; ++nb) {
                int cr = n0w + nb * 8 + g;
                float4 Bf = *(const float4*)(Bp + cr * B_STRIDE + p * 16 + t * 4);
                #pragma unroll
                for (int mb = 0; mb < 2; ++mb) {
                    MMA_TF32(acc[mb][nb][0], acc[mb][nb][1], acc[mb][nb][2], acc[mb][nb][3],
                             __float_as_uint(Af[mb][0].x), __float_as_uint(Af[mb][1].x),
                             __float_as_uint(Af[mb][0].y), __float_as_uint(Af[mb][1].y),
                             __float_as_uint(Bf.x), __float_as_uint(Bf.y));
                    MMA_TF32(acc[mb][nb][0], acc[mb][nb][1], acc[mb][nb][2], acc[mb][nb][3],
                             __float_as_uint(Af[mb][0].z), __float_as_uint(Af[mb][1].z),
                             __float_as_uint(Af[mb][0].w), __float_as_uint(Af[mb][1].w),
                             __float_as_uint(Bf.z), __float_as_uint(Bf.w));
                }
            }
        }
        // store prefetched tile into the other buffer
        if (tile < 63) {
            float* Bn = (float*)(smem_ + B_OFF((tile + 1) & 1));
            #pragma unroll
            for (int i = 0; i < 4; ++i) {
                const float* e4 = (const float*)&pf[i];
                #pragma unroll
                for (int j = 0; j < 4; ++j)
                    Bn[bc * B_STRIDE + seg * 16 + j * 4 + i] = e4[j];
            }
        }
        // epilogue at the end of each code-chunk
        if (dc == 7) {
            const int cc = tile >> 3;
            #pragma unroll
            for (int mb = 0; mb < 2; ++mb) {
                #pragma unroll
                for (int h = 0; h < 2; ++h) {
                    const int r4 = mb * 2 + h;
                    #pragma unroll
                    for (int nb = 0; nb < 8; ++nb) {
                        int c0 = cc * 128 + n0w + nb * 8 + 2 * t;
                        float sc0 = fmaf(-2.0f, acc[mb][nb][h * 2 + 0], en[c0]);
                        float sc1 = fmaf(-2.0f, acc[mb][nb][h * 2 + 1], en[c0 + 1]);
                        if (sc0 < s1[r4]) { s2[r4] = s1[r4]; i2[r4] = i1[r4]; s1[r4] = sc0; i1[r4] = c0; }
                        else if (sc0 < s2[r4]) { s2[r4] = sc0; i2[r4] = c0; }
                        if (sc1 < s1[r4]) { s2[r4] = s1[r4]; i2[r4] = i1[r4]; s1[r4] = sc1; i1[r4] = c0 + 1; }
                        else if (sc1 < s2[r4]) { s2[r4] = sc1; i2[r4] = c0 + 1; }
                    }
                }
            }
            #pragma unroll
            for (int a = 0; a < 2; ++a)
                #pragma unroll
                for (int b = 0; b < 8; ++b)
                    #pragma unroll
                    for (int c = 0; c < 4; ++c) acc[a][b][c] = 0.0f;
        }
        __syncthreads();
    }

    // ---- merge per-row candidates (8 owner threads x top-2) via smem ----
    float2* ms = (float2*)smem_;             // reuse A region
    int2*   mi = (int2*)(smem_ + 16384);
    const int slot = nw * 4 + t;
    #pragma unroll
    for (int r4 = 0; r4 < 4; ++r4) {
        int row = m0 + (r4 >> 1) * 16 + (r4 & 1) * 8 + g;
        ms[row * 8 + slot] = make_float2(s1[r4], s2[r4]);
        mi[row * 8 + slot] = make_int2(i1[r4], i2[r4]);
    }
    __syncthreads();

    if (tid < 128) {
        float b1 = 3.4e38f, b2 = 3.4e38f, b3 = 3.4e38f;
        int   j1 = 0, j2 = 0, j3 = 0;
        #pragma unroll
        for (int s = 0; s < 8; ++s) {
            float2 sv = ms[tid * 8 + s];
            int2   iv = mi[tid * 8 + s];
            float cs[2] = { sv.x, sv.y };
            int   ci[2] = { iv.x, iv.y };
            #pragma unroll
            for (int q = 0; q < 2; ++q) {
                float sc = cs[q]; int k = ci[q];
                if (sc < b1 || (sc == b1 && k < j1)) {
                    b3 = b2; j3 = j2; b2 = b1; j2 = j1; b1 = sc; j1 = k;
                } else if (sc < b2 || (sc == b2 && k < j2)) {
                    b3 = b2; j3 = j2; b2 = sc; j2 = k;
                } else if (sc < b3 || (sc == b3 && k < j3)) {
                    b3 = sc; j3 = k;
                }
            }
        }
        const int n = n0 + tid;
        if (b2 - b1 < GAP_TH) {
            int pos = atomicAdd(&g_flag_cnt, 1);
            int pk = j1 | (j2 << 10) | (j3 << 20) | ((b3 - b1 < GAP_TH) ? (1 << 30) : 0);
            g_fr_n[pos] = n;
            g_fr_c[pos] = pk;
        } else {
            g_idx[n] = j1;
            out_idx_f[n] = (float)j1;
        }
    }
}

// ---------------------------------------------------------------------------
// Kernel 1b: exact fp32 re-rank of flagged rows (one warp per row).
// ---------------------------------------------------------------------------
__global__ void __launch_bounds__(256)
recheck_kernel(const float* __restrict__ z, const float* __restrict__ emb,
               float* __restrict__ out_idx_f) {
    const int gw   = (blockIdx.x * 256 + threadIdx.x) >> 5;
    const int lane = threadIdx.x & 31;
    const int nwarp = gridDim.x * 8;
    const int cnt = g_flag_cnt;

    for (int f = gw; f < cnt; f += nwarp) {
        int n  = g_fr_n[f];
        int pk = g_fr_c[f];
        int cand[3];
        cand[0] = pk & 1023;
        cand[1] = (pk >> 10) & 1023;
        cand[2] = (pk >> 20) & 1023;
        int nc = (pk >> 30) ? 3 : 2;

        int b = n >> 12, hw = n & 4095;
        const float* zr = z + (size_t)b * (D_ * HW_) + hw;
        float zv[8];
        #pragma unroll
        for (int i = 0; i < 8; ++i) zv[i] = zr[(size_t)(lane + 32 * i) * HW_];

        float bs = 3.4e38f; int bi = 0;
        for (int q = 0; q < nc; ++q) {
            int cc = cand[q];
            const float* e = emb + cc * D_;
            float p = 0.0f;
            #pragma unroll
            for (int i = 0; i < 8; ++i) p = fmaf(zv[i], e[lane + 32 * i], p);
            #pragma unroll
            for (int off = 16; off > 0; off >>= 1)
                p += __shfl_down_sync(0xffffffffu, p, off);
            if (lane == 0) {
                float s = g_enorm[cc] - 2.0f * p;
                if (s < bs || (s == bs && cc < bi)) { bs = s; bi = cc; }
            }
        }
        if (lane == 0) { g_idx[n] = bi; out_idx_f[n] = (float)bi; }
    }
}

// ---------------------------------------------------------------------------
// Kernel 2 (v2): transpose-tiled gather. Block = 32 hw x 256 d for one b.
// Phase A: coalesced z loads -> smem (transposed, conflict-free stride 261).
// Phase B: warp-per-n -> emb row loads + dw atomics fully coalesced.
// Phase C: coalesced q stores from smem.
// ---------------------------------------------------------------------------
__global__ void __launch_bounds__(256)
gather_loss_dw_kernel(const float* __restrict__ z,
                      const float* __restrict__ emb,
                      float* __restrict__ out_q) {
    __shared__ float zt[32][261];
    __shared__ float wsum[8];

    const int tid  = threadIdx.x;
    const int lane = tid & 31;
    const int w    = tid >> 5;

    const int tile = blockIdx.x;          // 0..4095
    const int b    = tile >> 7;
    const int hw0  = (tile & 127) << 5;
    const float* zb = z     + (size_t)b * (D_ * HW_) + hw0;
    float*       ob = out_q + (size_t)b * (D_ * HW_) + hw0;

    // Phase A: coalesced load, transposed store (banks = 5*lane + d, distinct)
    #pragma unroll 8
    for (int i = 0; i < 32; ++i) {
        int d = w * 32 + i;
        zt[lane][d] = zb[(size_t)d * HW_ + lane];
    }
    __syncthreads();

    // Phase B: warp per n
    float lsum = 0.0f;
    #pragma unroll
    for (int pass = 0; pass < 4; ++pass) {
        const int hwl = w + 8 * pass;
        const int n   = (b << 12) + hw0 + hwl;
        const int idx = g_idx[n];
        const float* er = emb  + (size_t)idx * D_;
        float*       dr = g_dw + (size_t)idx * D_;
        if (lane == 0) atomicAdd(&g_counts[idx], 1.0f);
        #pragma unroll
        for (int j = 0; j < 8; ++j) {
            int d = lane + 32 * j;
            float zv = zt[hwl][d];
            float q  = er[d];
            float df = zv - q;
            lsum = fmaf(df, df, lsum);
            atomicAdd(&dr[d], zv);
            zt[hwl][d] = q;
        }
    }
    __syncthreads();

    // Phase C: coalesced store of quantized values
    #pragma unroll 8
    for (int i = 0; i < 32; ++i) {
        int d = w * 32 + i;
        ob[(size_t)d * HW_ + lane] = zt[lane][d];
    }

    // loss block-reduce -> one double atomic per block
    #pragma unroll
    for (int off = 16; off > 0; off >>= 1)
        lsum += __shfl_down_sync(0xffffffffu, lsum, off);
    if (lane == 0) wsum[w] = lsum;
    __syncthreads();
    if (w == 0) {
        float v = (lane < 8) ? wsum[lane] : 0.0f;
        #pragma unroll
        for (int off = 4; off > 0; off >>= 1)
            v += __shfl_down_sync(0xffffffffu, v, off);
        if (lane == 0) atomicAdd(&g_loss, (double)v);
    }
}

// ---------------------------------------------------------------------------
// Kernel 3: EMA updates + loss finalize
// ---------------------------------------------------------------------------
__global__ void finalize_kernel(const float* __restrict__ ema_cs,
                                const float* __restrict__ ema_emb,
                                float* __restrict__ out) {
    int i = blockIdx.x * 256 + threadIdx.x;
    const float decay = 0.99f;
    const float omd   = (float)(1.0 - 0.99);
    if (i < K_ * D_) out[OUT_EMB + i] = decay * ema_emb[i] + omd * g_dw[i];
    if (i < K_)      out[OUT_CS  + i] = decay * ema_cs[i]  + omd * g_counts[i];
    if (i == 0)      out[OUT_LOSS]    = 0.25f * (float)(g_loss / (double)TOTQ);
}

// ---------------------------------------------------------------------------
extern "C" void kernel_launch(void* const* d_in, const int* in_sizes, int n_in,
                              void* d_out, int out_size) {
    const float* z       = (const float*)d_in[0];
    const float* emb     = (const float*)d_in[1];
    const float* ema_cs  = (const float*)d_in[2];
    const float* ema_emb = (const float*)d_in[3];
    float* out = (float*)d_out;

    static int smem_set = 0;
    if (!smem_set) {
        cudaFuncSetAttribute(mma_argmin_kernel,
                             cudaFuncAttributeMaxDynamicSharedMemorySize, SMEM_TOTAL);
        smem_set = 1;
    }

    prep_kernel<<<1024, 256>>>(emb);
    mma_argmin_kernel<<<N_ / 128, 256, SMEM_TOTAL>>>(z, emb, out + OUT_IDX);
    recheck_kernel<<<256, 256>>>(z, emb, out + OUT_IDX);
    gather_loss_dw_kernel<<<4096, 256>>>(z, emb, out);
    finalize_kernel<<<1024, 256>>>(ema_cs, ema_emb, out);
}

// round 9
// speedup vs baseline: 2.0193x; 1.0112x over previous
#include <cuda_runtime.h>
#include <cstdint>

#define B_   32
#define D_   256
#define HW_  4096
#define N_   131072
#define K_   1024
#define TOTQ 33554432

#define OUT_LOSS 33554432
#define OUT_IDX  33554433
#define OUT_CS   33685505
#define OUT_EMB  33686529

#define GAP_TH 0.5f

__device__ float  g_enorm[K_];
__device__ float  g_Ep[K_ * D_];       // emb with permoff applied along d
__device__ int    g_idx[N_];
__device__ float  g_counts[K_];
__device__ float  g_dw[K_ * D_];
__device__ double g_loss;
__device__ int    g_flag_cnt;
__device__ int    g_fr_n[N_];
__device__ int    g_fr_c[N_];

// smem layout (bytes): A 128 rows x 272 floats (k-interleaved, padded),
// B 2 x (128 codes x 48 floats), enorm 1024 floats.
#define A_STRIDE   272
#define B_STRIDE   48
#define A_BYTES    139264                 // 128*272*4
#define B_OFF(i)   (A_BYTES + (i) * 24576)
#define EN_OFF     (A_BYTES + 49152)      // 188416
#define SMEM_TOTAL (EN_OFF + 4096)        // 192512

// interleaved position of d within its group of 16: 4x4 transpose (i*4+j -> j*4+i)
__device__ __forceinline__ int permoff(int d) {
    return ((d >> 4) << 4) + ((d & 3) << 2) + ((d & 15) >> 2);
}

#define MMA_TF32(c0, c1, c2, c3, a0, a1, a2, a3, b0, b1)                     \
    asm volatile("mma.sync.aligned.m16n8k8.row.col.f32.tf32.tf32.f32 "       \
        "{%0,%1,%2,%3}, {%4,%5,%6,%7}, {%8,%9}, {%0,%1,%2,%3};"              \
        : "+f"(c0), "+f"(c1), "+f"(c2), "+f"(c3)                             \
        : "r"(a0), "r"(a1), "r"(a2), "r"(a3), "r"(b0), "r"(b1))

// ---------------------------------------------------------------------------
// Kernel 0: zero scratch, exact ||e_k||^2, build permuted E
// ---------------------------------------------------------------------------
__global__ void prep_kernel(const float* __restrict__ emb) {
    int tid = blockIdx.x * blockDim.x + threadIdx.x;   // 262144 threads
    if (tid < K_ * D_) {
        g_dw[tid] = 0.0f;
        int k = tid >> 8, d = tid & 255;
        g_Ep[(k << 8) + permoff(d)] = emb[tid];
    }
    if (tid < K_) {
        g_counts[tid] = 0.0f;
        const float* e = emb + tid * D_;
        float s = 0.0f;
        #pragma unroll 8
        for (int d = 0; d < D_; ++d) { float v = e[d]; s += v * v; }
        g_enorm[tid] = s;
    }
    if (tid == 0) { g_loss = 0.0; g_flag_cnt = 0; }
}

// ---------------------------------------------------------------------------
// Kernel 1: TF32 mma.sync distance GEMM + fused argmin (top-2/thread,
// merged to top-3/row). Rows with small tf32 gap flagged for exact recheck.
// B tiles now straight-copied from pre-permuted g_Ep with STS.128.
// ---------------------------------------------------------------------------
__global__ void __launch_bounds__(256, 1)
mma_argmin_kernel(const float* __restrict__ z, const float* __restrict__ emb,
                  float* __restrict__ out_idx_f) {
    extern __shared__ __align__(16) char smem_[];
    float* As = (float*)smem_;
    float* en = (float*)(smem_ + EN_OFF);

    const int tid  = threadIdx.x;
    const int lane = tid & 31;
    const int wid  = tid >> 5;
    const int g    = lane >> 2;          // fragment group
    const int t    = lane & 3;           // thread-in-group
    const int mw   = wid >> 1;           // warp m index (0..3)
    const int nw   = wid & 1;            // warp n index (0..1)
    const int m0   = mw * 32;
    const int n0w  = nw * 64;

    const int n0  = blockIdx.x * 128;
    const int bb  = n0 >> 12;
    const int hw0 = n0 & 4095;
    const float* zb = z + (size_t)bb * (D_ * HW_) + hw0;

    // ---- A load: 128 rows x 256 d, interleaved layout ----
    {
        const int arow = tid & 127;
        const int ah   = tid >> 7;
        #pragma unroll 4
        for (int k = 0; k < 128; ++k) {
            int d = ah * 128 + k;
            As[arow * A_STRIDE + permoff(d)] = zb[(size_t)d * HW_ + arow];
        }
    }
    // ---- enorm -> smem ----
    #pragma unroll
    for (int i = 0; i < 4; ++i) en[tid + 256 * i] = g_enorm[tid + 256 * i];

    // ---- B tile loader: straight copy from g_Ep (code tid>>1, half tid&1) ----
    const int bc  = tid >> 1;
    const int seg = tid & 1;
    float4 pf[4];
    {   // prologue: tile 0 (cc=0, dc=0)
        const float4* src = (const float4*)(g_Ep + (size_t)bc * 256 + seg * 16);
        #pragma unroll
        for (int i = 0; i < 4; ++i) pf[i] = src[i];
        float4* Bp = (float4*)((float*)(smem_ + B_OFF(0)) + bc * B_STRIDE + seg * 16);
        #pragma unroll
        for (int j = 0; j < 4; ++j) Bp[j] = pf[j];
    }
    __syncthreads();

    float acc[2][8][4];
    float s1[4], s2[4];
    int   i1[4], i2[4];
    #pragma unroll
    for (int r = 0; r < 4; ++r) { s1[r] = 3.4e38f; s2[r] = 3.4e38f; i1[r] = 0; i2[r] = 0; }
    #pragma unroll
    for (int a = 0; a < 2; ++a)
        #pragma unroll
        for (int b = 0; b < 8; ++b)
            #pragma unroll
            for (int c = 0; c < 4; ++c) acc[a][b][c] = 0.0f;

    for (int tile = 0; tile < 64; ++tile) {
        const int dc = tile & 7;
        // prefetch next tile from gmem (L2-resident g_Ep)
        if (tile < 63) {
            int nt = tile + 1;
            const float4* src = (const float4*)(g_Ep
                + (size_t)((nt >> 3) * 128 + bc) * 256 + (nt & 7) * 32 + seg * 16);
            #pragma unroll
            for (int i = 0; i < 4; ++i) pf[i] = src[i];
        }
        // compute current tile: 4 k-steps (2 interleave groups x 2)
        const float* Bp = (const float*)(smem_ + B_OFF(tile & 1));
        #pragma unroll
        for (int p = 0; p < 2; ++p) {
            const int goff = (dc * 2 + p) * 16 + t * 4;     // float offset in A row
            float4 Af[2][2];
            #pragma unroll
            for (int mb = 0; mb < 2; ++mb) {
                int r0 = m0 + mb * 16 + g;
                Af[mb][0] = *(const float4*)(As + r0 * A_STRIDE + goff);
                Af[mb][1] = *(const float4*)(As + (r0 + 8) * A_STRIDE + goff);
            }
            #pragma unroll
            for (int nb = 0; nb < 8; ++nb) {
                int cr = n0w + nb * 8 + g;
                float4 Bf = *(const float4*)(Bp + cr * B_STRIDE + p * 16 + t * 4);
                #pragma unroll
                for (int mb = 0; mb < 2; ++mb) {
                    MMA_TF32(acc[mb][nb][0], acc[mb][nb][1], acc[mb][nb][2], acc[mb][nb][3],
                             __float_as_uint(Af[mb][0].x), __float_as_uint(Af[mb][1].x),
                             __float_as_uint(Af[mb][0].y), __float_as_uint(Af[mb][1].y),
                             __float_as_uint(Bf.x), __float_as_uint(Bf.y));
                    MMA_TF32(acc[mb][nb][0], acc[mb][nb][1], acc[mb][nb][2], acc[mb][nb][3],
                             __float_as_uint(Af[mb][0].z), __float_as_uint(Af[mb][1].z),
                             __float_as_uint(Af[mb][0].w), __float_as_uint(Af[mb][1].w),
                             __float_as_uint(Bf.z), __float_as_uint(Bf.w));
                }
            }
        }
        // store prefetched tile into the other buffer (4x STS.128)
        if (tile < 63) {
            float4* Bn = (float4*)((float*)(smem_ + B_OFF((tile + 1) & 1))
                                   + bc * B_STRIDE + seg * 16);
            #pragma unroll
            for (int j = 0; j < 4; ++j) Bn[j] = pf[j];
        }
        // epilogue at the end of each code-chunk
        if (dc == 7) {
            const int cc = tile >> 3;
            #pragma unroll
            for (int mb = 0; mb < 2; ++mb) {
                #pragma unroll
                for (int h = 0; h < 2; ++h) {
                    const int r4 = mb * 2 + h;
                    #pragma unroll
                    for (int nb = 0; nb < 8; ++nb) {
                        int c0 = cc * 128 + n0w + nb * 8 + 2 * t;
                        float sc0 = fmaf(-2.0f, acc[mb][nb][h * 2 + 0], en[c0]);
                        float sc1 = fmaf(-2.0f, acc[mb][nb][h * 2 + 1], en[c0 + 1]);
                        if (sc0 < s1[r4]) { s2[r4] = s1[r4]; i2[r4] = i1[r4]; s1[r4] = sc0; i1[r4] = c0; }
                        else if (sc0 < s2[r4]) { s2[r4] = sc0; i2[r4] = c0; }
                        if (sc1 < s1[r4]) { s2[r4] = s1[r4]; i2[r4] = i1[r4]; s1[r4] = sc1; i1[r4] = c0 + 1; }
                        else if (sc1 < s2[r4]) { s2[r4] = sc1; i2[r4] = c0 + 1; }
                    }
                }
            }
            #pragma unroll
            for (int a = 0; a < 2; ++a)
                #pragma unroll
                for (int b = 0; b < 8; ++b)
                    #pragma unroll
                    for (int c = 0; c < 4; ++c) acc[a][b][c] = 0.0f;
        }
        __syncthreads();
    }

    // ---- merge per-row candidates (8 owner threads x top-2) via smem ----
    float2* ms = (float2*)smem_;             // reuse A region
    int2*   mi = (int2*)(smem_ + 16384);
    const int slot = nw * 4 + t;
    #pragma unroll
    for (int r4 = 0; r4 < 4; ++r4) {
        int row = m0 + (r4 >> 1) * 16 + (r4 & 1) * 8 + g;
        ms[row * 8 + slot] = make_float2(s1[r4], s2[r4]);
        mi[row * 8 + slot] = make_int2(i1[r4], i2[r4]);
    }
    __syncthreads();

    if (tid < 128) {
        float b1 = 3.4e38f, b2 = 3.4e38f, b3 = 3.4e38f;
        int   j1 = 0, j2 = 0, j3 = 0;
        #pragma unroll
        for (int s = 0; s < 8; ++s) {
            float2 sv = ms[tid * 8 + s];
            int2   iv = mi[tid * 8 + s];
            float cs[2] = { sv.x, sv.y };
            int   ci[2] = { iv.x, iv.y };
            #pragma unroll
            for (int q = 0; q < 2; ++q) {
                float sc = cs[q]; int k = ci[q];
                if (sc < b1 || (sc == b1 && k < j1)) {
                    b3 = b2; j3 = j2; b2 = b1; j2 = j1; b1 = sc; j1 = k;
                } else if (sc < b2 || (sc == b2 && k < j2)) {
                    b3 = b2; j3 = j2; b2 = sc; j2 = k;
                } else if (sc < b3 || (sc == b3 && k < j3)) {
                    b3 = sc; j3 = k;
                }
            }
        }
        const int n = n0 + tid;
        if (b2 - b1 < GAP_TH) {
            int pos = atomicAdd(&g_flag_cnt, 1);
            int pk = j1 | (j2 << 10) | (j3 << 20) | ((b3 - b1 < GAP_TH) ? (1 << 30) : 0);
            g_fr_n[pos] = n;
            g_fr_c[pos] = pk;
        } else {
            g_idx[n] = j1;
            out_idx_f[n] = (float)j1;
        }
    }
}

// ---------------------------------------------------------------------------
// Kernel 1b: exact fp32 re-rank of flagged rows (one warp per row).
// ---------------------------------------------------------------------------
__global__ void __launch_bounds__(256)
recheck_kernel(const float* __restrict__ z, const float* __restrict__ emb,
               float* __restrict__ out_idx_f) {
    const int gw   = (blockIdx.x * 256 + threadIdx.x) >> 5;
    const int lane = threadIdx.x & 31;
    const int nwarp = gridDim.x * 8;
    const int cnt = g_flag_cnt;

    for (int f = gw; f < cnt; f += nwarp) {
        int n  = g_fr_n[f];
        int pk = g_fr_c[f];
        int cand[3];
        cand[0] = pk & 1023;
        cand[1] = (pk >> 10) & 1023;
        cand[2] = (pk >> 20) & 1023;
        int nc = (pk >> 30) ? 3 : 2;

        int b = n >> 12, hw = n & 4095;
        const float* zr = z + (size_t)b * (D_ * HW_) + hw;
        float zv[8];
        #pragma unroll
        for (int i = 0; i < 8; ++i) zv[i] = zr[(size_t)(lane + 32 * i) * HW_];

        float bs = 3.4e38f; int bi = 0;
        for (int q = 0; q < nc; ++q) {
            int cc = cand[q];
            const float* e = emb + cc * D_;
            float p = 0.0f;
            #pragma unroll
            for (int i = 0; i < 8; ++i) p = fmaf(zv[i], e[lane + 32 * i], p);
            #pragma unroll
            for (int off = 16; off > 0; off >>= 1)
                p += __shfl_down_sync(0xffffffffu, p, off);
            if (lane == 0) {
                float s = g_enorm[cc] - 2.0f * p;
                if (s < bs || (s == bs && cc < bi)) { bs = s; bi = cc; }
            }
        }
        if (lane == 0) { g_idx[n] = bi; out_idx_f[n] = (float)bi; }
    }
}

// ---------------------------------------------------------------------------
// Kernel 2: transpose-tiled gather. Block = 32 hw x 256 d for one b.
// ---------------------------------------------------------------------------
__global__ void __launch_bounds__(256)
gather_loss_dw_kernel(const float* __restrict__ z,
                      const float* __restrict__ emb,
                      float* __restrict__ out_q) {
    __shared__ float zt[32][261];
    __shared__ float wsum[8];

    const int tid  = threadIdx.x;
    const int lane = tid & 31;
    const int w    = tid >> 5;

    const int tile = blockIdx.x;          // 0..4095
    const int b    = tile >> 7;
    const int hw0  = (tile & 127) << 5;
    const float* zb = z     + (size_t)b * (D_ * HW_) + hw0;
    float*       ob = out_q + (size_t)b * (D_ * HW_) + hw0;

    #pragma unroll 8
    for (int i = 0; i < 32; ++i) {
        int d = w * 32 + i;
        zt[lane][d] = zb[(size_t)d * HW_ + lane];
    }
    __syncthreads();

    float lsum = 0.0f;
    #pragma unroll
    for (int pass = 0; pass < 4; ++pass) {
        const int hwl = w + 8 * pass;
        const int n   = (b << 12) + hw0 + hwl;
        const int idx = g_idx[n];
        const float* er = emb  + (size_t)idx * D_;
        float*       dr = g_dw + (size_t)idx * D_;
        if (lane == 0) atomicAdd(&g_counts[idx], 1.0f);
        #pragma unroll
        for (int j = 0; j < 8; ++j) {
            int d = lane + 32 * j;
            float zv = zt[hwl][d];
            float q  = er[d];
            float df = zv - q;
            lsum = fmaf(df, df, lsum);
            atomicAdd(&dr[d], zv);
            zt[hwl][d] = q;
        }
    }
    __syncthreads();

    #pragma unroll 8
    for (int i = 0; i < 32; ++i) {
        int d = w * 32 + i;
        ob[(size_t)d * HW_ + lane] = zt[lane][d];
    }

    #pragma unroll
    for (int off = 16; off > 0; off >>= 1)
        lsum += __shfl_down_sync(0xffffffffu, lsum, off);
    if (lane == 0) wsum[w] = lsum;
    __syncthreads();
    if (w == 0) {
        float v = (lane < 8) ? wsum[lane] : 0.0f;
        #pragma unroll
        for (int off = 4; off > 0; off >>= 1)
            v += __shfl_down_sync(0xffffffffu, v, off);
        if (lane == 0) atomicAdd(&g_loss, (double)v);
    }
}

// ---------------------------------------------------------------------------
// Kernel 3: EMA updates + loss finalize
// ---------------------------------------------------------------------------
__global__ void finalize_kernel(const float* __restrict__ ema_cs,
                                const float* __restrict__ ema_emb,
                                float* __restrict__ out) {
    int i = blockIdx.x * 256 + threadIdx.x;
    const float decay = 0.99f;
    const float omd   = (float)(1.0 - 0.99);
    if (i < K_ * D_) out[OUT_EMB + i] = decay * ema_emb[i] + omd * g_dw[i];
    if (i < K_)      out[OUT_CS  + i] = decay * ema_cs[i]  + omd * g_counts[i];
    if (i == 0)      out[OUT_LOSS]    = 0.25f * (float)(g_loss / (double)TOTQ);
}

// ---------------------------------------------------------------------------
extern "C" void kernel_launch(void* const* d_in, const int* in_sizes, int n_in,
                              void* d_out, int out_size) {
    const float* z       = (const float*)d_in[0];
    const float* emb     = (const float*)d_in[1];
    const float* ema_cs  = (const float*)d_in[2];
    const float* ema_emb = (const float*)d_in[3];
    float* out = (float*)d_out;

    static int smem_set = 0;
    if (!smem_set) {
        cudaFuncSetAttribute(mma_argmin_kernel,
                             cudaFuncAttributeMaxDynamicSharedMemorySize, SMEM_TOTAL);
        smem_set = 1;
    }

    prep_kernel<<<1024, 256>>>(emb);
    mma_argmin_kernel<<<N_ / 128, 256, SMEM_TOTAL>>>(z, emb, out + OUT_IDX);
    recheck_kernel<<<256, 256>>>(z, emb, out + OUT_IDX);
    gather_loss_dw_kernel<<<4096, 256>>>(z, emb, out);
    finalize_kernel<<<1024, 256>>>(ema_cs, ema_emb, out);
}

// round 10
// speedup vs baseline: 2.0344x; 1.0075x over previous
#include <cuda_runtime.h>
#include <cstdint>

#define B_   32
#define D_   256
#define HW_  4096
#define N_   131072
#define K_   1024
#define TOTQ 33554432

#define OUT_LOSS 33554432
#define OUT_IDX  33554433
#define OUT_CS   33685505
#define OUT_EMB  33686529

#define GAP_TH 0.5f

__device__ float  g_enorm[K_];
__device__ float  g_Ep[K_ * D_];       // emb with permoff applied along d
__device__ int    g_idx[N_];
__device__ float  g_counts[K_];
__device__ float  g_dw[K_ * D_];
__device__ double g_loss;
__device__ int    g_flag_cnt;
__device__ int    g_fr_n[N_];
__device__ int    g_fr_c[N_];

// smem layout (bytes): A 128 rows x 256 floats (swizzled), B 2 x (128 x 32
// floats, swizzled), enorm 1024 floats.
#define A_BYTES    131072                 // 128*256*4
#define B_OFF(i)   (A_BYTES + (i) * 16384)
#define EN_OFF     (A_BYTES + 32768)      // 163840
#define SMEM_TOTAL (EN_OFF + 4096)        // 167936

// interleaved position of d within its group of 16: 4x4 transpose (i*4+j -> j*4+i)
__device__ __forceinline__ int permoff(int d) {
    return ((d >> 4) << 4) + ((d & 3) << 2) + ((d & 15) >> 2);
}

#define MMA_TF32(c0, c1, c2, c3, a0, a1, a2, a3, b0, b1)                     \
    asm volatile("mma.sync.aligned.m16n8k8.row.col.f32.tf32.tf32.f32 "       \
        "{%0,%1,%2,%3}, {%4,%5,%6,%7}, {%8,%9}, {%0,%1,%2,%3};"              \
        : "+f"(c0), "+f"(c1), "+f"(c2), "+f"(c3)                             \
        : "r"(a0), "r"(a1), "r"(a2), "r"(a3), "r"(b0), "r"(b1))

// ---------------------------------------------------------------------------
// Kernel 0: zero scratch, exact ||e_k||^2, build permuted E
// ---------------------------------------------------------------------------
__global__ void prep_kernel(const float* __restrict__ emb) {
    int tid = blockIdx.x * blockDim.x + threadIdx.x;   // 262144 threads
    if (tid < K_ * D_) {
        g_dw[tid] = 0.0f;
        int k = tid >> 8, d = tid & 255;
        g_Ep[(k << 8) + permoff(d)] = emb[tid];
    }
    if (tid < K_) {
        g_counts[tid] = 0.0f;
        const float* e = emb + tid * D_;
        float s = 0.0f;
        #pragma unroll 8
        for (int d = 0; d < D_; ++d) { float v = e[d]; s += v * v; }
        g_enorm[tid] = s;
    }
    if (tid == 0) { g_loss = 0.0; g_flag_cnt = 0; }
}

// ---------------------------------------------------------------------------
// Kernel 1: TF32 mma.sync distance GEMM + fused argmin. Smem tiles use a
// quad-XOR bank swizzle (conflict-free fragment LDS.128).
// ---------------------------------------------------------------------------
__global__ void __launch_bounds__(256, 1)
mma_argmin_kernel(const float* __restrict__ z, const float* __restrict__ emb,
                  float* __restrict__ out_idx_f) {
    extern __shared__ __align__(16) char smem_[];
    float* As = (float*)smem_;
    float* en = (float*)(smem_ + EN_OFF);

    const int tid  = threadIdx.x;
    const int lane = tid & 31;
    const int wid  = tid >> 5;
    const int g    = lane >> 2;          // fragment group
    const int t    = lane & 3;           // thread-in-group
    const int mw   = wid >> 1;           // warp m index (0..3)
    const int nw   = wid & 1;            // warp n index (0..1)
    const int m0   = mw * 32;
    const int n0w  = nw * 64;

    const int n0  = blockIdx.x * 128;
    const int bb  = n0 >> 12;
    const int hw0 = n0 & 4095;
    const float* zb = z + (size_t)bb * (D_ * HW_) + hw0;

    // ---- A load: 128 rows x 256 d, interleaved + swizzled layout ----
    {
        const int arow = tid & 127;
        const int ah   = tid >> 7;
        const int rx   = arow & 7;
        #pragma unroll 4
        for (int k = 0; k < 128; ++k) {
            int d = ah * 128 + k;
            int c = permoff(d);
            As[arow * 256 + ((((c >> 2) ^ rx)) << 2) + (c & 3)]
                = zb[(size_t)d * HW_ + arow];
        }
    }
    // ---- enorm -> smem ----
    #pragma unroll
    for (int i = 0; i < 4; ++i) en[tid + 256 * i] = g_enorm[tid + 256 * i];

    // ---- B tile loader: copy from g_Ep, swizzled store (code tid>>1, half tid&1) ----
    const int bc  = tid >> 1;
    const int seg = tid & 1;
    const int bx  = bc & 7;
    float4 pf[4];
    {   // prologue: tile 0 (cc=0, dc=0)
        const float4* src = (const float4*)(g_Ep + (size_t)bc * 256 + seg * 16);
        #pragma unroll
        for (int i = 0; i < 4; ++i) pf[i] = src[i];
        float* Bp = (float*)(smem_ + B_OFF(0));
        #pragma unroll
        for (int j = 0; j < 4; ++j)
            *(float4*)(Bp + bc * 32 + (((seg * 4 + j) ^ bx) << 2)) = pf[j];
    }
    __syncthreads();

    float acc[2][8][4];
    float s1[4], s2[4];
    int   i1[4], i2[4];
    #pragma unroll
    for (int r = 0; r < 4; ++r) { s1[r] = 3.4e38f; s2[r] = 3.4e38f; i1[r] = 0; i2[r] = 0; }
    #pragma unroll
    for (int a = 0; a < 2; ++a)
        #pragma unroll
        for (int b = 0; b < 8; ++b)
            #pragma unroll
            for (int c = 0; c < 4; ++c) acc[a][b][c] = 0.0f;

    for (int tile = 0; tile < 64; ++tile) {
        const int dc = tile & 7;
        // prefetch next tile from gmem (L2-resident g_Ep)
        if (tile < 63) {
            int nt = tile + 1;
            const float4* src = (const float4*)(g_Ep
                + (size_t)((nt >> 3) * 128 + bc) * 256 + (nt & 7) * 32 + seg * 16);
            #pragma unroll
            for (int i = 0; i < 4; ++i) pf[i] = src[i];
        }
        // compute current tile: 4 k-steps (2 interleave groups x 2)
        const float* Bp = (const float*)(smem_ + B_OFF(tile & 1));
        #pragma unroll
        for (int p = 0; p < 2; ++p) {
            const int aq = ((dc * 2 + p) * 4 + t) ^ g;      // swizzled A quad
            float4 Af[2][2];
            #pragma unroll
            for (int mb = 0; mb < 2; ++mb) {
                int r0 = m0 + mb * 16 + g;
                Af[mb][0] = *(const float4*)(As + r0 * 256 + (aq << 2));
                Af[mb][1] = *(const float4*)(As + (r0 + 8) * 256 + (aq << 2));
            }
            const int bq = ((p * 4 + t) ^ g) << 2;          // swizzled B offset
            #pragma unroll
            for (int nb = 0; nb < 8; ++nb) {
                int cr = n0w + nb * 8 + g;
                float4 Bf = *(const float4*)(Bp + cr * 32 + bq);
                #pragma unroll
                for (int mb = 0; mb < 2; ++mb) {
                    MMA_TF32(acc[mb][nb][0], acc[mb][nb][1], acc[mb][nb][2], acc[mb][nb][3],
                             __float_as_uint(Af[mb][0].x), __float_as_uint(Af[mb][1].x),
                             __float_as_uint(Af[mb][0].y), __float_as_uint(Af[mb][1].y),
                             __float_as_uint(Bf.x), __float_as_uint(Bf.y));
                    MMA_TF32(acc[mb][nb][0], acc[mb][nb][1], acc[mb][nb][2], acc[mb][nb][3],
                             __float_as_uint(Af[mb][0].z), __float_as_uint(Af[mb][1].z),
                             __float_as_uint(Af[mb][0].w), __float_as_uint(Af[mb][1].w),
                             __float_as_uint(Bf.z), __float_as_uint(Bf.w));
                }
            }
        }
        // store prefetched tile into the other buffer (4x STS.128, swizzled)
        if (tile < 63) {
            float* Bn = (float*)(smem_ + B_OFF((tile + 1) & 1));
            #pragma unroll
            for (int j = 0; j < 4; ++j)
                *(float4*)(Bn + bc * 32 + (((seg * 4 + j) ^ bx) << 2)) = pf[j];
        }
        // epilogue at the end of each code-chunk
        if (dc == 7) {
            const int cc = tile >> 3;
            #pragma unroll
            for (int mb = 0; mb < 2; ++mb) {
                #pragma unroll
                for (int h = 0; h < 2; ++h) {
                    const int r4 = mb * 2 + h;
                    #pragma unroll
                    for (int nb = 0; nb < 8; ++nb) {
                        int c0 = cc * 128 + n0w + nb * 8 + 2 * t;
                        float sc0 = fmaf(-2.0f, acc[mb][nb][h * 2 + 0], en[c0]);
                        float sc1 = fmaf(-2.0f, acc[mb][nb][h * 2 + 1], en[c0 + 1]);
                        if (sc0 < s1[r4]) { s2[r4] = s1[r4]; i2[r4] = i1[r4]; s1[r4] = sc0; i1[r4] = c0; }
                        else if (sc0 < s2[r4]) { s2[r4] = sc0; i2[r4] = c0; }
                        if (sc1 < s1[r4]) { s2[r4] = s1[r4]; i2[r4] = i1[r4]; s1[r4] = sc1; i1[r4] = c0 + 1; }
                        else if (sc1 < s2[r4]) { s2[r4] = sc1; i2[r4] = c0 + 1; }
                    }
                }
            }
            #pragma unroll
            for (int a = 0; a < 2; ++a)
                #pragma unroll
                for (int b = 0; b < 8; ++b)
                    #pragma unroll
                    for (int c = 0; c < 4; ++c) acc[a][b][c] = 0.0f;
        }
        __syncthreads();
    }

    // ---- merge per-row candidates (8 owner threads x top-2) via smem ----
    float2* ms = (float2*)smem_;             // reuse A region
    int2*   mi = (int2*)(smem_ + 16384);
    const int slot = nw * 4 + t;
    #pragma unroll
    for (int r4 = 0; r4 < 4; ++r4) {
        int row = m0 + (r4 >> 1) * 16 + (r4 & 1) * 8 + g;
        ms[row * 8 + slot] = make_float2(s1[r4], s2[r4]);
        mi[row * 8 + slot] = make_int2(i1[r4], i2[r4]);
    }
    __syncthreads();

    if (tid < 128) {
        float b1 = 3.4e38f, b2 = 3.4e38f, b3 = 3.4e38f;
        int   j1 = 0, j2 = 0, j3 = 0;
        #pragma unroll
        for (int s = 0; s < 8; ++s) {
            float2 sv = ms[tid * 8 + s];
            int2   iv = mi[tid * 8 + s];
            float cs[2] = { sv.x, sv.y };
            int   ci[2] = { iv.x, iv.y };
            #pragma unroll
            for (int q = 0; q < 2; ++q) {
                float sc = cs[q]; int k = ci[q];
                if (sc < b1 || (sc == b1 && k < j1)) {
                    b3 = b2; j3 = j2; b2 = b1; j2 = j1; b1 = sc; j1 = k;
                } else if (sc < b2 || (sc == b2 && k < j2)) {
                    b3 = b2; j3 = j2; b2 = sc; j2 = k;
                } else if (sc < b3 || (sc == b3 && k < j3)) {
                    b3 = sc; j3 = k;
                }
            }
        }
        const int n = n0 + tid;
        if (b2 - b1 < GAP_TH) {
            int pos = atomicAdd(&g_flag_cnt, 1);
            int pk = j1 | (j2 << 10) | (j3 << 20) | ((b3 - b1 < GAP_TH) ? (1 << 30) : 0);
            g_fr_n[pos] = n;
            g_fr_c[pos] = pk;
        } else {
            g_idx[n] = j1;
            out_idx_f[n] = (float)j1;
        }
    }
}

// ---------------------------------------------------------------------------
// Kernel 1b: exact fp32 re-rank of flagged rows (one warp per row).
// ---------------------------------------------------------------------------
__global__ void __launch_bounds__(256)
recheck_kernel(const float* __restrict__ z, const float* __restrict__ emb,
               float* __restrict__ out_idx_f) {
    const int gw   = (blockIdx.x * 256 + threadIdx.x) >> 5;
    const int lane = threadIdx.x & 31;
    const int nwarp = gridDim.x * 8;
    const int cnt = g_flag_cnt;

    for (int f = gw; f < cnt; f += nwarp) {
        int n  = g_fr_n[f];
        int pk = g_fr_c[f];
        int cand[3];
        cand[0] = pk & 1023;
        cand[1] = (pk >> 10) & 1023;
        cand[2] = (pk >> 20) & 1023;
        int nc = (pk >> 30) ? 3 : 2;

        int b = n >> 12, hw = n & 4095;
        const float* zr = z + (size_t)b * (D_ * HW_) + hw;
        float zv[8];
        #pragma unroll
        for (int i = 0; i < 8; ++i) zv[i] = zr[(size_t)(lane + 32 * i) * HW_];

        float bs = 3.4e38f; int bi = 0;
        for (int q = 0; q < nc; ++q) {
            int cc = cand[q];
            const float* e = emb + cc * D_;
            float p = 0.0f;
            #pragma unroll
            for (int i = 0; i < 8; ++i) p = fmaf(zv[i], e[lane + 32 * i], p);
            #pragma unroll
            for (int off = 16; off > 0; off >>= 1)
                p += __shfl_down_sync(0xffffffffu, p, off);
            if (lane == 0) {
                float s = g_enorm[cc] - 2.0f * p;
                if (s < bs || (s == bs && cc < bi)) { bs = s; bi = cc; }
            }
        }
        if (lane == 0) { g_idx[n] = bi; out_idx_f[n] = (float)bi; }
    }
}

// ---------------------------------------------------------------------------
// Kernel 2: transpose-tiled gather. Block = 32 hw x 256 d for one b.
// ---------------------------------------------------------------------------
__global__ void __launch_bounds__(256)
gather_loss_dw_kernel(const float* __restrict__ z,
                      const float* __restrict__ emb,
                      float* __restrict__ out_q) {
    __shared__ float zt[32][261];
    __shared__ float wsum[8];

    const int tid  = threadIdx.x;
    const int lane = tid & 31;
    const int w    = tid >> 5;

    const int tile = blockIdx.x;          // 0..4095
    const int b    = tile >> 7;
    const int hw0  = (tile & 127) << 5;
    const float* zb = z     + (size_t)b * (D_ * HW_) + hw0;
    float*       ob = out_q + (size_t)b * (D_ * HW_) + hw0;

    #pragma unroll 8
    for (int i = 0; i < 32; ++i) {
        int d = w * 32 + i;
        zt[lane][d] = zb[(size_t)d * HW_ + lane];
    }
    __syncthreads();

    float lsum = 0.0f;
    #pragma unroll
    for (int pass = 0; pass < 4; ++pass) {
        const int hwl = w + 8 * pass;
        const int n   = (b << 12) + hw0 + hwl;
        const int idx = g_idx[n];
        const float* er = emb  + (size_t)idx * D_;
        float*       dr = g_dw + (size_t)idx * D_;
        if (lane == 0) atomicAdd(&g_counts[idx], 1.0f);
        #pragma unroll
        for (int j = 0; j < 8; ++j) {
            int d = lane + 32 * j;
            float zv = zt[hwl][d];
            float q  = er[d];
            float df = zv - q;
            lsum = fmaf(df, df, lsum);
            atomicAdd(&dr[d], zv);
            zt[hwl][d] = q;
        }
    }
    __syncthreads();

    #pragma unroll 8
    for (int i = 0; i < 32; ++i) {
        int d = w * 32 + i;
        ob[(size_t)d * HW_ + lane] = zt[lane][d];
    }

    #pragma unroll
    for (int off = 16; off > 0; off >>= 1)
        lsum += __shfl_down_sync(0xffffffffu, lsum, off);
    if (lane == 0) wsum[w] = lsum;
    __syncthreads();
    if (w == 0) {
        float v = (lane < 8) ? wsum[lane] : 0.0f;
        #pragma unroll
        for (int off = 4; off > 0; off >>= 1)
            v += __shfl_down_sync(0xffffffffu, v, off);
        if (lane == 0) atomicAdd(&g_loss, (double)v);
    }
}

// ---------------------------------------------------------------------------
// Kernel 3: EMA updates + loss finalize
// ---------------------------------------------------------------------------
__global__ void finalize_kernel(const float* __restrict__ ema_cs,
                                const float* __restrict__ ema_emb,
                                float* __restrict__ out) {
    int i = blockIdx.x * 256 + threadIdx.x;
    const float decay = 0.99f;
    const float omd   = (float)(1.0 - 0.99);
    if (i < K_ * D_) out[OUT_EMB + i] = decay * ema_emb[i] + omd * g_dw[i];
    if (i < K_)      out[OUT_CS  + i] = decay * ema_cs[i]  + omd * g_counts[i];
    if (i == 0)      out[OUT_LOSS]    = 0.25f * (float)(g_loss / (double)TOTQ);
}

// ---------------------------------------------------------------------------
extern "C" void kernel_launch(void* const* d_in, const int* in_sizes, int n_in,
                              void* d_out, int out_size) {
    const float* z       = (const float*)d_in[0];
    const float* emb     = (const float*)d_in[1];
    const float* ema_cs  = (const float*)d_in[2];
    const float* ema_emb = (const float*)d_in[3];
    float* out = (float*)d_out;

    static int smem_set = 0;
    if (!smem_set) {
        cudaFuncSetAttribute(mma_argmin_kernel,
                             cudaFuncAttributeMaxDynamicSharedMemorySize, SMEM_TOTAL);
        smem_set = 1;
    }

    prep_kernel<<<1024, 256>>>(emb);
    mma_argmin_kernel<<<N_ / 128, 256, SMEM_TOTAL>>>(z, emb, out + OUT_IDX);
    recheck_kernel<<<256, 256>>>(z, emb, out + OUT_IDX);
    gather_loss_dw_kernel<<<4096, 256>>>(z, emb, out);
    finalize_kernel<<<1024, 256>>>(ema_cs, ema_emb, out);
}

// round 11
// speedup vs baseline: 2.9141x; 1.4324x over previous
#include <cuda_runtime.h>
#include <cuda_bf16.h>
#include <cstdint>

#define B_   32
#define D_   256
#define HW_  4096
#define N_   131072
#define K_   1024
#define TOTQ 33554432

#define OUT_LOSS 33554432
#define OUT_IDX  33554433
#define OUT_CS   33685505
#define OUT_EMB  33686529

#define GAP_TH 0.5f

__device__ float    g_enorm[K_];
__device__ uint32_t g_Ebf[K_ * D_ / 2];   // emb as packed bf16x2, row-major
__device__ int      g_idx[N_];
__device__ float    g_counts[K_];
__device__ float    g_dw[K_ * D_];
__device__ double   g_loss;
__device__ int      g_flag_cnt;
__device__ int      g_fr_n[N_];
__device__ int      g_fr_c[N_];

// smem: A = 128 rows x 512B bf16 (32 16B-units/row, XOR-swizzled) = 64KB
//       B = 2 x (64 codes x 512B, same swizzle) = 64KB ; enorm 4KB
#define A_OFF      0
#define B_OFF(i)   (65536 + (i) * 32768)
#define EN_OFF     131072
#define SMEM_TOTAL 135168

__device__ __forceinline__ uint32_t smem_u32(const void* p) {
    uint32_t a;
    asm("{ .reg .u64 t; cvta.to.shared.u64 t, %1; cvt.u32.u64 %0, t; }" : "=r"(a) : "l"(p));
    return a;
}
__device__ __forceinline__ uint32_t bf2(float lo, float hi) {
    __nv_bfloat162 h = __floats2bfloat162_rn(lo, hi);   // x=lo(bits 0-15), y=hi
    return *reinterpret_cast<uint32_t*>(&h);
}
#define LDSM4(r, addr)                                                        \
    asm volatile("ldmatrix.sync.aligned.m8n8.x4.shared.b16 {%0,%1,%2,%3}, [%4];" \
        : "=r"((r)[0]), "=r"((r)[1]), "=r"((r)[2]), "=r"((r)[3]) : "r"(addr))
#define MMA_BF16(c, a, b0, b1)                                                \
    asm volatile("mma.sync.aligned.m16n8k16.row.col.f32.bf16.bf16.f32 "       \
        "{%0,%1,%2,%3},{%4,%5,%6,%7},{%8,%9},{%0,%1,%2,%3};"                  \
        : "+f"((c)[0]), "+f"((c)[1]), "+f"((c)[2]), "+f"((c)[3])              \
        : "r"((a)[0]), "r"((a)[1]), "r"((a)[2]), "r"((a)[3]), "r"(b0), "r"(b1))

#define TOP3_UPD(rs, sc, k)                                                               \
    if ((sc) < s1[rs]) { s3[rs]=s2[rs]; i3[rs]=i2[rs]; s2[rs]=s1[rs]; i2[rs]=i1[rs];      \
                         s1[rs]=(sc); i1[rs]=(k); }                                       \
    else if ((sc) < s2[rs]) { s3[rs]=s2[rs]; i3[rs]=i2[rs]; s2[rs]=(sc); i2[rs]=(k); }    \
    else if ((sc) < s3[rs]) { s3[rs]=(sc); i3[rs]=(k); }

// ---------------------------------------------------------------------------
// Kernel 0: zero scratch, exact ||e_k||^2, pack E to bf16
// ---------------------------------------------------------------------------
__global__ void prep_kernel(const float* __restrict__ emb) {
    int tid = blockIdx.x * blockDim.x + threadIdx.x;   // 262144 threads
    if (tid < K_ * D_) g_dw[tid] = 0.0f;
    if (tid < K_ * D_ / 2) {
        float2 v = ((const float2*)emb)[tid];
        g_Ebf[tid] = bf2(v.x, v.y);
    }
    if (tid < K_) {
        g_counts[tid] = 0.0f;
        const float* e = emb + tid * D_;
        float s = 0.0f;
        #pragma unroll 8
        for (int d = 0; d < D_; ++d) { float v = e[d]; s += v * v; }
        g_enorm[tid] = s;
    }
    if (tid == 0) { g_loss = 0.0; g_flag_cnt = 0; }
}

// Dummy kernels: shift the ncu skip window so the MMA kernel gets profiled.
__global__ void dummy1_kernel() { if (threadIdx.x == 0) g_loss = 0.0; }
__global__ void dummy2_kernel() { if (threadIdx.x == 0) g_flag_cnt = 0; }

// ---------------------------------------------------------------------------
// Kernel 1: bf16 m16n8k16 mma.sync distance GEMM (ldmatrix fragments) +
// fused per-row top-3 argmin; small-gap rows flagged for exact recheck.
// 512 threads = 4x4 warp grid, warp tile 32 rows x 16 codes, chunks of 64
// codes over all K, full D per chunk (16 k-steps of k16).
// ---------------------------------------------------------------------------
__global__ void __launch_bounds__(512, 1)
mma_argmin_kernel(const float* __restrict__ z, float* __restrict__ out_idx_f) {
    extern __shared__ __align__(16) char smem_[];
    const uint32_t smb = smem_u32(smem_);
    float* en = (float*)(smem_ + EN_OFF);

    const int tid   = threadIdx.x;
    const int lane  = tid & 31;
    const int wid   = tid >> 5;
    const int g     = lane >> 2;
    const int t     = lane & 3;
    const int warpM = wid >> 2;          // 0..3
    const int warpN = wid & 3;           // 0..3
    const int r0    = warpM * 32;
    const int c0t   = warpN * 16;        // code offset within 64-code tile

    const int n0  = blockIdx.x * 128;
    const int bb  = n0 >> 12;
    const int hw0 = n0 & 4095;
    const float* zb = z + (size_t)bb * (D_ * HW_) + hw0;

    // ---- A load: convert z rows to bf16, swizzled 16B units ----
    {
        const int row = tid & 127, dh = tid >> 7, rx = row & 7;
        #pragma unroll
        for (int u = 0; u < 8; ++u) {
            float v[8];
            #pragma unroll
            for (int j = 0; j < 8; ++j)
                v[j] = zb[(size_t)(dh * 64 + u * 8 + j) * HW_ + row];
            uint4 w = { bf2(v[0], v[1]), bf2(v[2], v[3]),
                        bf2(v[4], v[5]), bf2(v[6], v[7]) };
            int gu = dh * 8 + u;
            *(uint4*)(smem_ + A_OFF + row * 512 + ((gu ^ rx) << 4)) = w;
        }
    }
    en[tid] = g_enorm[tid];
    en[tid + 512] = g_enorm[tid + 512];

    // ---- B tile loader: 64 codes x 512B, swizzled ----
    const int bcode = tid >> 3;          // 0..63
    const int bu0   = (tid & 7) * 4;
    const int bx    = bcode & 7;
    uint4 pf[4];
    {
        const uint4* src = (const uint4*)g_Ebf;   // idx = code*32 + unit
        #pragma unroll
        for (int j = 0; j < 4; ++j) pf[j] = src[(size_t)bcode * 32 + bu0 + j];
        #pragma unroll
        for (int j = 0; j < 4; ++j)
            *(uint4*)(smem_ + B_OFF(0) + bcode * 512 + (((bu0 + j) ^ bx) << 4)) = pf[j];
    }
    __syncthreads();

    float acc[2][2][4];
    #pragma unroll
    for (int a = 0; a < 2; ++a)
        #pragma unroll
        for (int b = 0; b < 2; ++b)
            #pragma unroll
            for (int q = 0; q < 4; ++q) acc[a][b][q] = 0.0f;

    float s1[4], s2[4], s3[4];
    int   i1[4], i2[4], i3[4];
    #pragma unroll
    for (int r = 0; r < 4; ++r) {
        s1[r] = 3.4e38f; s2[r] = 3.4e38f; s3[r] = 3.4e38f;
        i1[r] = 0; i2[r] = 0; i3[r] = 0;
    }

    // ldmatrix per-lane address components
    const int ls  = lane >> 3;                       // matrix select 0..3
    const int a_r = (lane & 7) + ((ls & 1) << 3);    // A: m0/m2 rows 0-7, m1/m3 rows 8-15
    const int a_q = ls >> 1;                         // A: m0/m1 unit q0, m2/m3 q1
    const int b_r = (lane & 7) + ((ls >> 1) << 3);   // B: m0/m1 codes 0-7, m2/m3 codes 8-15
    const int b_q = ls & 1;                          // B: m0/m2 unit q0, m1/m3 q1

    for (int c = 0; c < 16; ++c) {
        if (c < 15) {
            const uint4* src = (const uint4*)g_Ebf;
            #pragma unroll
            for (int j = 0; j < 4; ++j)
                pf[j] = src[(size_t)((c + 1) * 64 + bcode) * 32 + bu0 + j];
        }
        const uint32_t Bb = smb + B_OFF(c & 1);
        #pragma unroll 4
        for (int ks = 0; ks < 16; ++ks) {
            const int q0 = 2 * ks;
            uint32_t a0[4], a1[4], bf[4];
            {
                int r = r0 + a_r;
                LDSM4(a0, smb + A_OFF + r * 512 + (((q0 + a_q) ^ (r & 7)) << 4));
                int r2 = r + 16;
                LDSM4(a1, smb + A_OFF + r2 * 512 + (((q0 + a_q) ^ (r2 & 7)) << 4));
            }
            {
                int cr = c0t + b_r;
                LDSM4(bf, Bb + cr * 512 + (((q0 + b_q) ^ (cr & 7)) << 4));
            }
            MMA_BF16(acc[0][0], a0, bf[0], bf[1]);
            MMA_BF16(acc[0][1], a0, bf[2], bf[3]);
            MMA_BF16(acc[1][0], a1, bf[0], bf[1]);
            MMA_BF16(acc[1][1], a1, bf[2], bf[3]);
        }
        if (c < 15) {
            #pragma unroll
            for (int j = 0; j < 4; ++j)
                *(uint4*)(smem_ + B_OFF((c + 1) & 1) + bcode * 512
                          + (((bu0 + j) ^ bx) << 4)) = pf[j];
        }
        // chunk epilogue: scores + per-slot top-3
        #pragma unroll
        for (int mb = 0; mb < 2; ++mb) {
            #pragma unroll
            for (int half = 0; half < 2; ++half) {
                const int rs = mb * 2 + half;
                #pragma unroll
                for (int nbb = 0; nbb < 2; ++nbb) {
                    const int cb = c * 64 + warpN * 16 + nbb * 8 + 2 * t;
                    float sc0 = fmaf(-2.0f, acc[mb][nbb][half * 2 + 0], en[cb]);
                    float sc1 = fmaf(-2.0f, acc[mb][nbb][half * 2 + 1], en[cb + 1]);
                    TOP3_UPD(rs, sc0, cb);
                    TOP3_UPD(rs, sc1, cb + 1);
                }
            }
        }
        #pragma unroll
        for (int a = 0; a < 2; ++a)
            #pragma unroll
            for (int b = 0; b < 2; ++b)
                #pragma unroll
                for (int q = 0; q < 4; ++q) acc[a][b][q] = 0.0f;
        __syncthreads();
    }

    // ---- merge per-row candidates: 16 owner slots x top-3, via smem ----
    float4* ms = (float4*)smem_;                 // 128 x 16 x 16B = 32KB
    int4*   mi = (int4*)(smem_ + 32768);         // 32KB
    const int slot = warpN * 4 + t;
    #pragma unroll
    for (int rs = 0; rs < 4; ++rs) {
        int row = r0 + (rs >> 1) * 16 + (rs & 1) * 8 + g;
        ms[row * 16 + slot] = make_float4(s1[rs], s2[rs], s3[rs], 0.0f);
        mi[row * 16 + slot] = make_int4(i1[rs], i2[rs], i3[rs], 0);
    }
    __syncthreads();

    if (tid < 128) {
        float b1 = 3.4e38f, b2 = 3.4e38f, b3 = 3.4e38f;
        int   j1 = 0, j2 = 0, j3 = 0;
        #pragma unroll
        for (int s = 0; s < 16; ++s) {
            float4 sv = ms[tid * 16 + s];
            int4   iv = mi[tid * 16 + s];
            float cs[3] = { sv.x, sv.y, sv.z };
            int   ci[3] = { iv.x, iv.y, iv.z };
            #pragma unroll
            for (int q = 0; q < 3; ++q) {
                float sc = cs[q]; int k = ci[q];
                if (sc < b1 || (sc == b1 && k < j1)) {
                    b3 = b2; j3 = j2; b2 = b1; j2 = j1; b1 = sc; j1 = k;
                } else if (sc < b2 || (sc == b2 && k < j2)) {
                    b3 = b2; j3 = j2; b2 = sc; j2 = k;
                } else if (sc < b3 || (sc == b3 && k < j3)) {
                    b3 = sc; j3 = k;
                }
            }
        }
        const int n = n0 + tid;
        if (b2 - b1 < GAP_TH) {
            int pos = atomicAdd(&g_flag_cnt, 1);
            int pk = j1 | (j2 << 10) | (j3 << 20) | ((b3 - b1 < GAP_TH) ? (1 << 30) : 0);
            g_fr_n[pos] = n;
            g_fr_c[pos] = pk;
        } else {
            g_idx[n] = j1;
            out_idx_f[n] = (float)j1;
        }
    }
}

// ---------------------------------------------------------------------------
// Kernel 1b: exact fp32 re-rank of flagged rows (one warp per row).
// ---------------------------------------------------------------------------
__global__ void __launch_bounds__(256)
recheck_kernel(const float* __restrict__ z, const float* __restrict__ emb,
               float* __restrict__ out_idx_f) {
    const int gw   = (blockIdx.x * 256 + threadIdx.x) >> 5;
    const int lane = threadIdx.x & 31;
    const int nwarp = gridDim.x * 8;
    const int cnt = g_flag_cnt;

    for (int f = gw; f < cnt; f += nwarp) {
        int n  = g_fr_n[f];
        int pk = g_fr_c[f];
        int cand[3];
        cand[0] = pk & 1023;
        cand[1] = (pk >> 10) & 1023;
        cand[2] = (pk >> 20) & 1023;
        int nc = (pk >> 30) ? 3 : 2;

        int b = n >> 12, hw = n & 4095;
        const float* zr = z + (size_t)b * (D_ * HW_) + hw;
        float zv[8];
        #pragma unroll
        for (int i = 0; i < 8; ++i) zv[i] = zr[(size_t)(lane + 32 * i) * HW_];

        float bs = 3.4e38f; int bi = 0;
        for (int q = 0; q < nc; ++q) {
            int cc = cand[q];
            const float* e = emb + cc * D_;
            float p = 0.0f;
            #pragma unroll
            for (int i = 0; i < 8; ++i) p = fmaf(zv[i], e[lane + 32 * i], p);
            #pragma unroll
            for (int off = 16; off > 0; off >>= 1)
                p += __shfl_down_sync(0xffffffffu, p, off);
            if (lane == 0) {
                float s = g_enorm[cc] - 2.0f * p;
                if (s < bs || (s == bs && cc < bi)) { bs = s; bi = cc; }
            }
        }
        if (lane == 0) { g_idx[n] = bi; out_idx_f[n] = (float)bi; }
    }
}

// ---------------------------------------------------------------------------
// Kernel 2: transpose-tiled gather. Block = 32 hw x 256 d for one b.
// ---------------------------------------------------------------------------
__global__ void __launch_bounds__(256)
gather_loss_dw_kernel(const float* __restrict__ z,
                      const float* __restrict__ emb,
                      float* __restrict__ out_q) {
    __shared__ float zt[32][261];
    __shared__ float wsum[8];

    const int tid  = threadIdx.x;
    const int lane = tid & 31;
    const int w    = tid >> 5;

    const int tile = blockIdx.x;          // 0..4095
    const int b    = tile >> 7;
    const int hw0  = (tile & 127) << 5;
    const float* zb = z     + (size_t)b * (D_ * HW_) + hw0;
    float*       ob = out_q + (size_t)b * (D_ * HW_) + hw0;

    #pragma unroll 8
    for (int i = 0; i < 32; ++i) {
        int d = w * 32 + i;
        zt[lane][d] = zb[(size_t)d * HW_ + lane];
    }
    __syncthreads();

    float lsum = 0.0f;
    #pragma unroll
    for (int pass = 0; pass < 4; ++pass) {
        const int hwl = w + 8 * pass;
        const int n   = (b << 12) + hw0 + hwl;
        const int idx = g_idx[n];
        const float* er = emb  + (size_t)idx * D_;
        float*       dr = g_dw + (size_t)idx * D_;
        if (lane == 0) atomicAdd(&g_counts[idx], 1.0f);
        #pragma unroll
        for (int j = 0; j < 8; ++j) {
            int d = lane + 32 * j;
            float zv = zt[hwl][d];
            float q  = er[d];
            float df = zv - q;
            lsum = fmaf(df, df, lsum);
            atomicAdd(&dr[d], zv);
            zt[hwl][d] = q;
        }
    }
    __syncthreads();

    #pragma unroll 8
    for (int i = 0; i < 32; ++i) {
        int d = w * 32 + i;
        ob[(size_t)d * HW_ + lane] = zt[lane][d];
    }

    #pragma unroll
    for (int off = 16; off > 0; off >>= 1)
        lsum += __shfl_down_sync(0xffffffffu, lsum, off);
    if (lane == 0) wsum[w] = lsum;
    __syncthreads();
    if (w == 0) {
        float v = (lane < 8) ? wsum[lane] : 0.0f;
        #pragma unroll
        for (int off = 4; off > 0; off >>= 1)
            v += __shfl_down_sync(0xffffffffu, v, off);
        if (lane == 0) atomicAdd(&g_loss, (double)v);
    }
}

// ---------------------------------------------------------------------------
// Kernel 3: EMA updates + loss finalize
// ---------------------------------------------------------------------------
__global__ void finalize_kernel(const float* __restrict__ ema_cs,
                                const float* __restrict__ ema_emb,
                                float* __restrict__ out) {
    int i = blockIdx.x * 256 + threadIdx.x;
    const float decay = 0.99f;
    const float omd   = (float)(1.0 - 0.99);
    if (i < K_ * D_) out[OUT_EMB + i] = decay * ema_emb[i] + omd * g_dw[i];
    if (i < K_)      out[OUT_CS  + i] = decay * ema_cs[i]  + omd * g_counts[i];
    if (i == 0)      out[OUT_LOSS]    = 0.25f * (float)(g_loss / (double)TOTQ);
}

// ---------------------------------------------------------------------------
extern "C" void kernel_launch(void* const* d_in, const int* in_sizes, int n_in,
                              void* d_out, int out_size) {
    const float* z       = (const float*)d_in[0];
    const float* emb     = (const float*)d_in[1];
    const float* ema_cs  = (const float*)d_in[2];
    const float* ema_emb = (const float*)d_in[3];
    float* out = (float*)d_out;

    static int smem_set = 0;
    if (!smem_set) {
        cudaFuncSetAttribute(mma_argmin_kernel,
                             cudaFuncAttributeMaxDynamicSharedMemorySize, SMEM_TOTAL);
        smem_set = 1;
    }

    prep_kernel<<<1024, 256>>>(emb);
    dummy1_kernel<<<1, 32>>>();
    dummy2_kernel<<<1, 32>>>();
    mma_argmin_kernel<<<N_ / 128, 512, SMEM_TOTAL>>>(z, out + OUT_IDX);
    recheck_kernel<<<256, 256>>>(z, emb, out + OUT_IDX);
    gather_loss_dw_kernel<<<4096, 256>>>(z, emb, out);
    finalize_kernel<<<1024, 256>>>(ema_cs, ema_emb, out);
}

// round 12
// speedup vs baseline: 3.1515x; 1.0815x over previous
#include <cuda_runtime.h>
#include <cuda_bf16.h>
#include <cstdint>

#define B_   32
#define D_   256
#define HW_  4096
#define N_   131072
#define K_   1024
#define TOTQ 33554432

#define OUT_LOSS 33554432
#define OUT_IDX  33554433
#define OUT_CS   33685505
#define OUT_EMB  33686529

#define GAP_TH 0.5f

__device__ float    g_enorm[K_];
__device__ uint32_t g_Ebf[K_ * D_ / 2];   // emb as packed bf16x2, row-major
__device__ int      g_idx[N_];
__device__ float    g_counts[K_];
__device__ float    g_dw[K_ * D_];
__device__ double   g_loss;
__device__ int      g_flag_cnt;
__device__ int      g_fr_n[N_];
__device__ int      g_fr_c[N_];

// smem: A = 128 rows x 512B bf16 (XOR-swizzled 16B units) = 64KB
//       B = 2 x (128 codes x 512B, same swizzle) = 128KB ; enorm 4KB
#define A_OFF      0
#define B_OFF(i)   (65536 + (i) * 65536)
#define EN_OFF     196608
#define SMEM_TOTAL 200704

__device__ __forceinline__ uint32_t smem_u32(const void* p) {
    uint32_t a;
    asm("{ .reg .u64 t; cvta.to.shared.u64 t, %1; cvt.u32.u64 %0, t; }" : "=r"(a) : "l"(p));
    return a;
}
__device__ __forceinline__ uint32_t bf2(float lo, float hi) {
    __nv_bfloat162 h = __floats2bfloat162_rn(lo, hi);
    return *reinterpret_cast<uint32_t*>(&h);
}
#define LDSM4(r, addr)                                                        \
    asm volatile("ldmatrix.sync.aligned.m8n8.x4.shared.b16 {%0,%1,%2,%3}, [%4];" \
        : "=r"((r)[0]), "=r"((r)[1]), "=r"((r)[2]), "=r"((r)[3]) : "r"(addr))
#define MMA_BF16(c, a, b0, b1)                                                \
    asm volatile("mma.sync.aligned.m16n8k16.row.col.f32.bf16.bf16.f32 "       \
        "{%0,%1,%2,%3},{%4,%5,%6,%7},{%8,%9},{%0,%1,%2,%3};"                  \
        : "+f"((c)[0]), "+f"((c)[1]), "+f"((c)[2]), "+f"((c)[3])              \
        : "r"((a)[0]), "r"((a)[1]), "r"((a)[2]), "r"((a)[3]), "r"(b0), "r"(b1))
#define CP_ASYNC16(dst, src)                                                  \
    asm volatile("cp.async.cg.shared.global [%0], [%1], 16;" :: "r"(dst), "l"(src))
#define CP_COMMIT()  asm volatile("cp.async.commit_group;" ::: "memory")
#define CP_WAIT(n)   asm volatile("cp.async.wait_group %0;" :: "n"(n) : "memory")

#define TOP3_UPD(rs, sc, k)                                                               \
    if ((sc) < s1[rs]) { s3[rs]=s2[rs]; i3[rs]=i2[rs]; s2[rs]=s1[rs]; i2[rs]=i1[rs];      \
                         s1[rs]=(sc); i1[rs]=(k); }                                       \
    else if ((sc) < s2[rs]) { s3[rs]=s2[rs]; i3[rs]=i2[rs]; s2[rs]=(sc); i2[rs]=(k); }    \
    else if ((sc) < s3[rs]) { s3[rs]=(sc); i3[rs]=(k); }

// ---------------------------------------------------------------------------
// Kernel 0: zero scratch, exact ||e_k||^2, pack E to bf16
// ---------------------------------------------------------------------------
__global__ void prep_kernel(const float* __restrict__ emb) {
    int tid = blockIdx.x * blockDim.x + threadIdx.x;   // 262144 threads
    if (tid < K_ * D_) g_dw[tid] = 0.0f;
    if (tid < K_ * D_ / 2) {
        float2 v = ((const float2*)emb)[tid];
        g_Ebf[tid] = bf2(v.x, v.y);
    }
    if (tid < K_) {
        g_counts[tid] = 0.0f;
        const float* e = emb + tid * D_;
        float s = 0.0f;
        #pragma unroll 8
        for (int d = 0; d < D_; ++d) { float v = e[d]; s += v * v; }
        g_enorm[tid] = s;
    }
    if (tid == 0) { g_loss = 0.0; g_flag_cnt = 0; }
}

// Dummy kernels: keep the ncu skip window on the MMA kernel.
__global__ void dummy1_kernel() { if (threadIdx.x == 0) g_loss = 0.0; }
__global__ void dummy2_kernel() { if (threadIdx.x == 0) g_flag_cnt = 0; }

// ---------------------------------------------------------------------------
// Kernel 1: bf16 m16n8k16 GEMM + fused top-3 argmin.
// 16 warps, 4m x 4n grid, warp tile 32 rows x 32 codes, chunk = 128 codes
// (8 chunks), B double-buffered via cp.async.
// ---------------------------------------------------------------------------
__global__ void __launch_bounds__(512, 1)
mma_argmin_kernel(const float* __restrict__ z, float* __restrict__ out_idx_f) {
    extern __shared__ __align__(16) char smem_[];
    const uint32_t smb = smem_u32(smem_);
    float* en = (float*)(smem_ + EN_OFF);

    const int tid   = threadIdx.x;
    const int lane  = tid & 31;
    const int wid   = tid >> 5;
    const int g     = lane >> 2;
    const int t     = lane & 3;
    const int warpM = wid >> 2;          // 0..3
    const int warpN = wid & 3;           // 0..3
    const int r0    = warpM * 32;
    const int c0t   = warpN * 32;        // code offset within 128-code chunk

    const int n0  = blockIdx.x * 128;
    const int bb  = n0 >> 12;
    const int hw0 = n0 & 4095;
    const float* zb = z + (size_t)bb * (D_ * HW_) + hw0;

    // ---- A load: convert z rows to bf16, swizzled 16B units ----
    {
        const int row = tid & 127, dh = tid >> 7, rx = row & 7;
        #pragma unroll
        for (int u = 0; u < 8; ++u) {
            float v[8];
            #pragma unroll
            for (int j = 0; j < 8; ++j)
                v[j] = zb[(size_t)(dh * 64 + u * 8 + j) * HW_ + row];
            uint4 w = { bf2(v[0], v[1]), bf2(v[2], v[3]),
                        bf2(v[4], v[5]), bf2(v[6], v[7]) };
            int gu = dh * 8 + u;
            *(uint4*)(smem_ + A_OFF + row * 512 + ((gu ^ rx) << 4)) = w;
        }
    }
    en[tid] = g_enorm[tid];
    en[tid + 512] = g_enorm[tid + 512];

    // ---- B tiles via cp.async: 128 codes x 512B per chunk ----
    const int bcode = tid >> 2;          // 0..127
    const int bu0   = (tid & 3) * 8;     // 8 16B-units per thread
    const int bx    = bcode & 7;
    {
        const uint4* src = (const uint4*)g_Ebf;    // idx = code*32 + unit
        #pragma unroll
        for (int j = 0; j < 8; ++j)
            CP_ASYNC16(smb + B_OFF(0) + bcode * 512 + (((bu0 + j) ^ bx) << 4),
                       src + (size_t)bcode * 32 + bu0 + j);
        CP_COMMIT();
    }
    __syncthreads();   // A + en visible

    float acc[2][4][4];
    #pragma unroll
    for (int a = 0; a < 2; ++a)
        #pragma unroll
        for (int b = 0; b < 4; ++b)
            #pragma unroll
            for (int q = 0; q < 4; ++q) acc[a][b][q] = 0.0f;

    float s1[4], s2[4], s3[4];
    int   i1[4], i2[4], i3[4];
    #pragma unroll
    for (int r = 0; r < 4; ++r) {
        s1[r] = 3.4e38f; s2[r] = 3.4e38f; s3[r] = 3.4e38f;
        i1[r] = 0; i2[r] = 0; i3[r] = 0;
    }

    // ldmatrix per-lane address components
    const int ls  = lane >> 3;
    const int a_r = (lane & 7) + ((ls & 1) << 3);
    const int a_q = ls >> 1;
    const int b_r = (lane & 7) + ((ls >> 1) << 3);
    const int b_q = ls & 1;

    for (int c = 0; c < 8; ++c) {
        if (c < 7) {
            const uint4* src = (const uint4*)g_Ebf;
            #pragma unroll
            for (int j = 0; j < 8; ++j)
                CP_ASYNC16(smb + B_OFF((c + 1) & 1) + bcode * 512
                               + (((bu0 + j) ^ bx) << 4),
                           src + (size_t)((c + 1) * 128 + bcode) * 32 + bu0 + j);
            CP_COMMIT();
            CP_WAIT(1);            // chunk c's group complete
        } else {
            CP_WAIT(0);
        }
        __syncthreads();

        const uint32_t Bb = smb + B_OFF(c & 1);
        #pragma unroll 4
        for (int ks = 0; ks < 16; ++ks) {
            const int q0 = 2 * ks;
            uint32_t a0[4], a1[4], bf0[4], bf1[4];
            {
                int r = r0 + a_r;
                LDSM4(a0, smb + A_OFF + r * 512 + (((q0 + a_q) ^ (r & 7)) << 4));
                int r2 = r + 16;
                LDSM4(a1, smb + A_OFF + r2 * 512 + (((q0 + a_q) ^ (r2 & 7)) << 4));
            }
            {
                int cr = c0t + b_r;
                LDSM4(bf0, Bb + cr * 512 + (((q0 + b_q) ^ (cr & 7)) << 4));
                int cr2 = cr + 16;
                LDSM4(bf1, Bb + cr2 * 512 + (((q0 + b_q) ^ (cr2 & 7)) << 4));
            }
            MMA_BF16(acc[0][0], a0, bf0[0], bf0[1]);
            MMA_BF16(acc[0][1], a0, bf0[2], bf0[3]);
            MMA_BF16(acc[0][2], a0, bf1[0], bf1[1]);
            MMA_BF16(acc[0][3], a0, bf1[2], bf1[3]);
            MMA_BF16(acc[1][0], a1, bf0[0], bf0[1]);
            MMA_BF16(acc[1][1], a1, bf0[2], bf0[3]);
            MMA_BF16(acc[1][2], a1, bf1[0], bf1[1]);
            MMA_BF16(acc[1][3], a1, bf1[2], bf1[3]);
        }
        // chunk epilogue: scores + per-slot top-3
        #pragma unroll
        for (int mb = 0; mb < 2; ++mb) {
            #pragma unroll
            for (int half = 0; half < 2; ++half) {
                const int rs = mb * 2 + half;
                #pragma unroll
                for (int nbb = 0; nbb < 4; ++nbb) {
                    const int cb = c * 128 + c0t + nbb * 8 + 2 * t;
                    float sc0 = fmaf(-2.0f, acc[mb][nbb][half * 2 + 0], en[cb]);
                    float sc1 = fmaf(-2.0f, acc[mb][nbb][half * 2 + 1], en[cb + 1]);
                    TOP3_UPD(rs, sc0, cb);
                    TOP3_UPD(rs, sc1, cb + 1);
                }
            }
        }
        #pragma unroll
        for (int a = 0; a < 2; ++a)
            #pragma unroll
            for (int b = 0; b < 4; ++b)
                #pragma unroll
                for (int q = 0; q < 4; ++q) acc[a][b][q] = 0.0f;
        __syncthreads();   // all reads of buf (c&1) done before c+2 overwrites
    }

    // ---- merge per-row candidates: 16 owner slots x top-3, via smem ----
    float4* ms = (float4*)smem_;
    int4*   mi = (int4*)(smem_ + 32768);
    const int slot = warpN * 4 + t;
    #pragma unroll
    for (int rs = 0; rs < 4; ++rs) {
        int row = r0 + (rs >> 1) * 16 + (rs & 1) * 8 + g;
        ms[row * 16 + slot] = make_float4(s1[rs], s2[rs], s3[rs], 0.0f);
        mi[row * 16 + slot] = make_int4(i1[rs], i2[rs], i3[rs], 0);
    }
    __syncthreads();

    if (tid < 128) {
        float b1 = 3.4e38f, b2 = 3.4e38f, b3 = 3.4e38f;
        int   j1 = 0, j2 = 0, j3 = 0;
        #pragma unroll
        for (int s = 0; s < 16; ++s) {
            float4 sv = ms[tid * 16 + s];
            int4   iv = mi[tid * 16 + s];
            float cs[3] = { sv.x, sv.y, sv.z };
            int   ci[3] = { iv.x, iv.y, iv.z };
            #pragma unroll
            for (int q = 0; q < 3; ++q) {
                float sc = cs[q]; int k = ci[q];
                if (sc < b1 || (sc == b1 && k < j1)) {
                    b3 = b2; j3 = j2; b2 = b1; j2 = j1; b1 = sc; j1 = k;
                } else if (sc < b2 || (sc == b2 && k < j2)) {
                    b3 = b2; j3 = j2; b2 = sc; j2 = k;
                } else if (sc < b3 || (sc == b3 && k < j3)) {
                    b3 = sc; j3 = k;
                }
            }
        }
        const int n = n0 + tid;
        if (b2 - b1 < GAP_TH) {
            int pos = atomicAdd(&g_flag_cnt, 1);
            int pk = j1 | (j2 << 10) | (j3 << 20) | ((b3 - b1 < GAP_TH) ? (1 << 30) : 0);
            g_fr_n[pos] = n;
            g_fr_c[pos] = pk;
        } else {
            g_idx[n] = j1;
            out_idx_f[n] = (float)j1;
        }
    }
}

// ---------------------------------------------------------------------------
// Kernel 1b: exact fp32 re-rank of flagged rows (one warp per row).
// ---------------------------------------------------------------------------
__global__ void __launch_bounds__(256)
recheck_kernel(const float* __restrict__ z, const float* __restrict__ emb,
               float* __restrict__ out_idx_f) {
    const int gw   = (blockIdx.x * 256 + threadIdx.x) >> 5;
    const int lane = threadIdx.x & 31;
    const int nwarp = gridDim.x * 8;
    const int cnt = g_flag_cnt;

    for (int f = gw; f < cnt; f += nwarp) {
        int n  = g_fr_n[f];
        int pk = g_fr_c[f];
        int cand[3];
        cand[0] = pk & 1023;
        cand[1] = (pk >> 10) & 1023;
        cand[2] = (pk >> 20) & 1023;
        int nc = (pk >> 30) ? 3 : 2;

        int b = n >> 12, hw = n & 4095;
        const float* zr = z + (size_t)b * (D_ * HW_) + hw;
        float zv[8];
        #pragma unroll
        for (int i = 0; i < 8; ++i) zv[i] = zr[(size_t)(lane + 32 * i) * HW_];

        float bs = 3.4e38f; int bi = 0;
        for (int q = 0; q < nc; ++q) {
            int cc = cand[q];
            const float* e = emb + cc * D_;
            float p = 0.0f;
            #pragma unroll
            for (int i = 0; i < 8; ++i) p = fmaf(zv[i], e[lane + 32 * i], p);
            #pragma unroll
            for (int off = 16; off > 0; off >>= 1)
                p += __shfl_down_sync(0xffffffffu, p, off);
            if (lane == 0) {
                float s = g_enorm[cc] - 2.0f * p;
                if (s < bs || (s == bs && cc < bi)) { bs = s; bi = cc; }
            }
        }
        if (lane == 0) { g_idx[n] = bi; out_idx_f[n] = (float)bi; }
    }
}

// ---------------------------------------------------------------------------
// Kernel 2: transpose-tiled gather. Block = 32 hw x 256 d for one b.
// ---------------------------------------------------------------------------
__global__ void __launch_bounds__(256)
gather_loss_dw_kernel(const float* __restrict__ z,
                      const float* __restrict__ emb,
                      float* __restrict__ out_q) {
    __shared__ float zt[32][261];
    __shared__ float wsum[8];

    const int tid  = threadIdx.x;
    const int lane = tid & 31;
    const int w    = tid >> 5;

    const int tile = blockIdx.x;          // 0..4095
    const int b    = tile >> 7;
    const int hw0  = (tile & 127) << 5;
    const float* zb = z     + (size_t)b * (D_ * HW_) + hw0;
    float*       ob = out_q + (size_t)b * (D_ * HW_) + hw0;

    #pragma unroll 8
    for (int i = 0; i < 32; ++i) {
        int d = w * 32 + i;
        zt[lane][d] = zb[(size_t)d * HW_ + lane];
    }
    __syncthreads();

    float lsum = 0.0f;
    #pragma unroll
    for (int pass = 0; pass < 4; ++pass) {
        const int hwl = w + 8 * pass;
        const int n   = (b << 12) + hw0 + hwl;
        const int idx = g_idx[n];
        const float* er = emb  + (size_t)idx * D_;
        float*       dr = g_dw + (size_t)idx * D_;
        if (lane == 0) atomicAdd(&g_counts[idx], 1.0f);
        #pragma unroll
        for (int j = 0; j < 8; ++j) {
            int d = lane + 32 * j;
            float zv = zt[hwl][d];
            float q  = er[d];
            float df = zv - q;
            lsum = fmaf(df, df, lsum);
            atomicAdd(&dr[d], zv);
            zt[hwl][d] = q;
        }
    }
    __syncthreads();

    #pragma unroll 8
    for (int i = 0; i < 32; ++i) {
        int d = w * 32 + i;
        ob[(size_t)d * HW_ + lane] = zt[lane][d];
    }

    #pragma unroll
    for (int off = 16; off > 0; off >>= 1)
        lsum += __shfl_down_sync(0xffffffffu, lsum, off);
    if (lane == 0) wsum[w] = lsum;
    __syncthreads();
    if (w == 0) {
        float v = (lane < 8) ? wsum[lane] : 0.0f;
        #pragma unroll
        for (int off = 4; off > 0; off >>= 1)
            v += __shfl_down_sync(0xffffffffu, v, off);
        if (lane == 0) atomicAdd(&g_loss, (double)v);
    }
}

// ---------------------------------------------------------------------------
// Kernel 3: EMA updates + loss finalize
// ---------------------------------------------------------------------------
__global__ void finalize_kernel(const float* __restrict__ ema_cs,
                                const float* __restrict__ ema_emb,
                                float* __restrict__ out) {
    int i = blockIdx.x * 256 + threadIdx.x;
    const float decay = 0.99f;
    const float omd   = (float)(1.0 - 0.99);
    if (i < K_ * D_) out[OUT_EMB + i] = decay * ema_emb[i] + omd * g_dw[i];
    if (i < K_)      out[OUT_CS  + i] = decay * ema_cs[i]  + omd * g_counts[i];
    if (i == 0)      out[OUT_LOSS]    = 0.25f * (float)(g_loss / (double)TOTQ);
}

// ---------------------------------------------------------------------------
extern "C" void kernel_launch(void* const* d_in, const int* in_sizes, int n_in,
                              void* d_out, int out_size) {
    const float* z       = (const float*)d_in[0];
    const float* emb     = (const float*)d_in[1];
    const float* ema_cs  = (const float*)d_in[2];
    const float* ema_emb = (const float*)d_in[3];
    float* out = (float*)d_out;

    static int smem_set = 0;
    if (!smem_set) {
        cudaFuncSetAttribute(mma_argmin_kernel,
                             cudaFuncAttributeMaxDynamicSharedMemorySize, SMEM_TOTAL);
        smem_set = 1;
    }

    prep_kernel<<<1024, 256>>>(emb);
    dummy1_kernel<<<1, 32>>>();
    dummy2_kernel<<<1, 32>>>();
    mma_argmin_kernel<<<N_ / 128, 512, SMEM_TOTAL>>>(z, out + OUT_IDX);
    recheck_kernel<<<256, 256>>>(z, emb, out + OUT_IDX);
    gather_loss_dw_kernel<<<4096, 256>>>(z, emb, out);
    finalize_kernel<<<1024, 256>>>(ema_cs, ema_emb, out);
}